// round 10
// baseline (speedup 1.0000x reference)
#include <cuda_runtime.h>

#define B_      32
#define H_      256
#define W_      256
#define TW      30          // output tile width
#define TH      30          // output tile height
#define RW      32          // stage-2 (delta) region = (TW+2)^2
#define CWD     34          // comb tile width  = TW+4
#define CHT     34          // comb tile height = TH+4
#define NTHR    256
#define N_STEPS 10

typedef unsigned long long u64;

// Ping-pong state, channels-last [B][H][W][16] as float4 x4
__device__ float4 g_state0[(size_t)B_ * H_ * W_ * 4];
__device__ float4 g_state1[(size_t)B_ * H_ * W_ * 4];
// Fused perceive->up1 weights: (W_up1 @ W_perceive): [16][17][9], bias [16]
__device__ float g_wf[16 * 17 * 9];
__device__ float g_bf[16];

__device__ __forceinline__ u64 pack2(float lo, float hi) {
    u64 r;
    asm("mov.b64 %0, {%1, %2};" : "=l"(r) : "f"(lo), "f"(hi));
    return r;
}
__device__ __forceinline__ void unpack2(u64 v, float& lo, float& hi) {
    asm("mov.b64 {%0, %1}, %2;" : "=f"(lo), "=f"(hi) : "l"(v));
}
__device__ __forceinline__ void fma2(u64& acc, u64 a, u64 b) {
    asm("fma.rn.f32x2 %0, %1, %2, %0;" : "+l"(acc) : "l"(a), "l"(b));
}
__device__ __forceinline__ float sigmoidf_(float z) {
    return 1.0f / (1.0f + __expf(-z));
}

struct SM {
    float comb[CHT][CWD][17];     // x + state, halo 2 (stride 17 conflict-free)
    float del [RW][RW][17];       // delta region, halo 1 (16 used, stride 17)
    ulonglong2 wf [17][9][4];     // fused conv 17->16 weights (out-ch quads)
    ulonglong2 wt [33][9][4];     // tau weights
    ulonglong2 wu2[16][4];        // up2
    u64 bf2[8];                   // fused bias pairs
    u64 bu22[8];
    u64 bt2[8];                   // b_tau_conv + b_tau
};

// ---- prep: fold up1 into perceive (both linear; relu is after up1) ----
extern "C" __global__ void fuse_weights(const float* __restrict__ wp,
                                        const float* __restrict__ bp,
                                        const float* __restrict__ w1,
                                        const float* __restrict__ b1)
{
    int i = blockIdx.x * blockDim.x + threadIdx.x;
    if (i < 16 * 153) {
        int o = i / 153, ck = i % 153;
        float s = 0.f;
        #pragma unroll
        for (int m = 0; m < 32; m++) s += w1[o * 32 + m] * wp[m * 153 + ck];
        g_wf[i] = s;
    }
    if (i < 16) {
        float s = b1[i];
        #pragma unroll
        for (int m = 0; m < 32; m++) s += w1[i * 32 + m] * bp[m];
        g_bf[i] = s;
    }
}

extern "C" __global__ void __launch_bounds__(NTHR)
nca_step(const float*  __restrict__ x,
         const float4* __restrict__ sIn,
         float4*       __restrict__ sOut,
         const float* __restrict__ w_up2,  const float* __restrict__ b_up2,
         const float* __restrict__ w_tau,  const float* __restrict__ b_tauc,
         const float* __restrict__ b_tau)
{
    extern __shared__ char smraw[];
    SM& sm = *reinterpret_cast<SM*>(smraw);

    const int tid = threadIdx.x;
    const int x0 = blockIdx.x * TW;
    const int y0 = blockIdx.y * TH;
    const int b  = blockIdx.z;

    // ---- pack weights into shared ----
    for (int i = tid; i < 17 * 9 * 4; i += NTHR) {         // fused conv
        int q = i & 3, k = (i >> 2) % 9, c = i / 36;
        int o = 4 * q;
        sm.wf[c][k][q] = make_ulonglong2(
            pack2(g_wf[(o + 0) * 153 + c * 9 + k], g_wf[(o + 1) * 153 + c * 9 + k]),
            pack2(g_wf[(o + 2) * 153 + c * 9 + k], g_wf[(o + 3) * 153 + c * 9 + k]));
    }
    for (int i = tid; i < 33 * 9 * 4; i += NTHR) {         // tau
        int q = i & 3, k = (i >> 2) % 9, c = i / 36;
        int o = 4 * q;
        sm.wt[c][k][q] = make_ulonglong2(
            pack2(w_tau[(o + 0) * 297 + c * 9 + k], w_tau[(o + 1) * 297 + c * 9 + k]),
            pack2(w_tau[(o + 2) * 297 + c * 9 + k], w_tau[(o + 3) * 297 + c * 9 + k]));
    }
    for (int i = tid; i < 16 * 4; i += NTHR) {             // up2
        int q = i & 3, ci = i >> 2;
        int o = 4 * q;
        sm.wu2[ci][q] = make_ulonglong2(
            pack2(w_up2[(o + 0) * 16 + ci], w_up2[(o + 1) * 16 + ci]),
            pack2(w_up2[(o + 2) * 16 + ci], w_up2[(o + 3) * 16 + ci]));
    }
    if (tid < 8) {
        sm.bf2[tid] = pack2(g_bf[2 * tid], g_bf[2 * tid + 1]);
    } else if (tid < 16) {
        int j = tid - 8;
        sm.bu22[j] = pack2(b_up2[2 * j], b_up2[2 * j + 1]);
    } else if (tid < 24) {
        int j = tid - 16;
        sm.bt2[j] = pack2(b_tauc[2 * j] + b_tau[2 * j],
                          b_tauc[2 * j + 1] + b_tau[2 * j + 1]);
    }

    // ---- load combined = [x, state] tile with halo 2 (zero padded) ----
    for (int p = tid; p < CHT * CWD; p += NTHR) {
        int cy = p / CWD, cx = p % CWD;
        int gy = y0 - 2 + cy, gx = x0 - 2 + cx;
        float* dst = &sm.comb[cy][cx][0];
        if ((unsigned)gy < H_ && (unsigned)gx < W_) {
            long pix = ((long)(b * H_ + gy)) * W_ + gx;
            dst[0] = x[pix];
            float4 s0 = sIn[pix * 4 + 0];
            float4 s1 = sIn[pix * 4 + 1];
            float4 s2 = sIn[pix * 4 + 2];
            float4 s3 = sIn[pix * 4 + 3];
            dst[1] = s0.x;  dst[2] = s0.y;  dst[3] = s0.z;  dst[4] = s0.w;
            dst[5] = s1.x;  dst[6] = s1.y;  dst[7] = s1.z;  dst[8] = s1.w;
            dst[9] = s2.x;  dst[10] = s2.y; dst[11] = s2.z; dst[12] = s2.w;
            dst[13] = s3.x; dst[14] = s3.y; dst[15] = s3.z; dst[16] = s3.w;
        } else {
            #pragma unroll
            for (int c = 0; c < 17; c++) dst[c] = 0.f;
        }
    }
    __syncthreads();

    // ---- stage 2: fused conv(17->16)+relu+up2(16->16) over 32x32 region,
    //      4 vertical px / thread (256 thr = 32 cols x 8 groups, exact) ----
    {
        const int rx  = tid & 31;        // 0..31
        const int ry4 = (tid >> 5) << 2; // 0,4,...,28
        const int gx  = x0 - 1 + rx;
        const int gy0 = y0 - 1 + ry4;

        const float* cb = &sm.comb[ry4][rx][0];   // window top-left for px0

        u64 acc[4][8];
        #pragma unroll
        for (int p = 0; p < 4; p++)
            #pragma unroll
            for (int j = 0; j < 8; j++) acc[p][j] = sm.bf2[j];

        #pragma unroll 1
        for (int c = 0; c < 17; c++) {
            const float* cc = cb + c;
            float v[18];   // 6 rows x 3 cols
            #pragma unroll
            for (int i = 0; i < 6; i++)
                #pragma unroll
                for (int j = 0; j < 3; j++)
                    v[i * 3 + j] = cc[(i * CWD + j) * 17];
            #pragma unroll
            for (int k = 0; k < 9; k++) {
                const int dy = k / 3, dx = k % 3;
                u64 t0 = pack2(v[(dy + 0) * 3 + dx], v[(dy + 0) * 3 + dx]);
                u64 t1 = pack2(v[(dy + 1) * 3 + dx], v[(dy + 1) * 3 + dx]);
                u64 t2 = pack2(v[(dy + 2) * 3 + dx], v[(dy + 2) * 3 + dx]);
                u64 t3 = pack2(v[(dy + 3) * 3 + dx], v[(dy + 3) * 3 + dx]);
                #pragma unroll
                for (int q = 0; q < 4; q++) {
                    ulonglong2 w = sm.wf[c][k][q];
                    fma2(acc[0][2 * q],     w.x, t0);
                    fma2(acc[0][2 * q + 1], w.y, t0);
                    fma2(acc[1][2 * q],     w.x, t1);
                    fma2(acc[1][2 * q + 1], w.y, t1);
                    fma2(acc[2][2 * q],     w.x, t2);
                    fma2(acc[2][2 * q + 1], w.y, t2);
                    fma2(acc[3][2 * q],     w.x, t3);
                    fma2(acc[3][2 * q + 1], w.y, t3);
                }
            }
        }

        // relu + up2 + store delta to smem, one pixel at a time
        #pragma unroll 1
        for (int p = 0; p < 4; p++) {
            float h[16];
            #pragma unroll
            for (int j = 0; j < 8; j++) {
                float a, bq;
                unpack2(acc[p][j], a, bq);
                h[2 * j]     = fmaxf(a, 0.f);
                h[2 * j + 1] = fmaxf(bq, 0.f);
            }
            u64 d[8];
            #pragma unroll
            for (int j = 0; j < 8; j++) d[j] = sm.bu22[j];
            #pragma unroll
            for (int ci = 0; ci < 16; ci++) {
                u64 pk = pack2(h[ci], h[ci]);
                #pragma unroll
                for (int q = 0; q < 4; q++) {
                    ulonglong2 w = sm.wu2[ci][q];
                    fma2(d[2 * q],     w.x, pk);
                    fma2(d[2 * q + 1], w.y, pk);
                }
            }
            const bool vp = (unsigned)gx < W_ && (unsigned)(gy0 + p) < H_;
            float* dd = &sm.del[ry4 + p][rx][0];
            #pragma unroll
            for (int j = 0; j < 8; j++) {
                float e0, e1;
                unpack2(d[j], e0, e1);
                dd[2 * j]     = vp ? e0 : 0.f;
                dd[2 * j + 1] = vp ? e1 : 0.f;
            }
        }
    }
    __syncthreads();

    // ---- stage 3: tau conv3x3 (33->16) + gated blend, 4 vertical px/thread
    //      (240 threads = 30 cols x 8 groups, clamped; dup rows idempotent) ----
    if (tid < 240) {
        const int ox  = tid % 30;
        const int g   = tid / 30;                    // 0..7
        const int oy4 = (4 * g < 26) ? 4 * g : 26;   // 0,4,...,24,26
        const int gx  = x0 + ox;

        const float* cb = &sm.comb[oy4 + 1][ox + 1][0];   // comb window base
        const float* db = &sm.del [oy4][ox][0];           // del window base

        u64 acc[4][8];
        #pragma unroll
        for (int p = 0; p < 4; p++)
            #pragma unroll
            for (int j = 0; j < 8; j++) acc[p][j] = sm.bt2[j];

        #pragma unroll 1
        for (int c = 0; c < 17; c++) {   // x + state channels from comb
            const float* cc = cb + c;
            float v[18];
            #pragma unroll
            for (int i = 0; i < 6; i++)
                #pragma unroll
                for (int j = 0; j < 3; j++)
                    v[i * 3 + j] = cc[(i * CWD + j) * 17];
            #pragma unroll
            for (int k = 0; k < 9; k++) {
                const int dy = k / 3, dx = k % 3;
                u64 t0 = pack2(v[(dy + 0) * 3 + dx], v[(dy + 0) * 3 + dx]);
                u64 t1 = pack2(v[(dy + 1) * 3 + dx], v[(dy + 1) * 3 + dx]);
                u64 t2 = pack2(v[(dy + 2) * 3 + dx], v[(dy + 2) * 3 + dx]);
                u64 t3 = pack2(v[(dy + 3) * 3 + dx], v[(dy + 3) * 3 + dx]);
                #pragma unroll
                for (int q = 0; q < 4; q++) {
                    ulonglong2 w = sm.wt[c][k][q];
                    fma2(acc[0][2 * q],     w.x, t0);
                    fma2(acc[0][2 * q + 1], w.y, t0);
                    fma2(acc[1][2 * q],     w.x, t1);
                    fma2(acc[1][2 * q + 1], w.y, t1);
                    fma2(acc[2][2 * q],     w.x, t2);
                    fma2(acc[2][2 * q + 1], w.y, t2);
                    fma2(acc[3][2 * q],     w.x, t3);
                    fma2(acc[3][2 * q + 1], w.y, t3);
                }
            }
        }
        #pragma unroll 1
        for (int c = 0; c < 16; c++) {   // delta channels from del
            const float* cc = db + c;
            float v[18];
            #pragma unroll
            for (int i = 0; i < 6; i++)
                #pragma unroll
                for (int j = 0; j < 3; j++)
                    v[i * 3 + j] = cc[(i * RW + j) * 17];
            #pragma unroll
            for (int k = 0; k < 9; k++) {
                const int dy = k / 3, dx = k % 3;
                u64 t0 = pack2(v[(dy + 0) * 3 + dx], v[(dy + 0) * 3 + dx]);
                u64 t1 = pack2(v[(dy + 1) * 3 + dx], v[(dy + 1) * 3 + dx]);
                u64 t2 = pack2(v[(dy + 2) * 3 + dx], v[(dy + 2) * 3 + dx]);
                u64 t3 = pack2(v[(dy + 3) * 3 + dx], v[(dy + 3) * 3 + dx]);
                #pragma unroll
                for (int q = 0; q < 4; q++) {
                    ulonglong2 w = sm.wt[17 + c][k][q];
                    fma2(acc[0][2 * q],     w.x, t0);
                    fma2(acc[0][2 * q + 1], w.y, t0);
                    fma2(acc[1][2 * q],     w.x, t1);
                    fma2(acc[1][2 * q + 1], w.y, t1);
                    fma2(acc[2][2 * q],     w.x, t2);
                    fma2(acc[2][2 * q + 1], w.y, t2);
                    fma2(acc[3][2 * q],     w.x, t3);
                    fma2(acc[3][2 * q + 1], w.y, t3);
                }
            }
        }

        // sigmoid gate + blend + store per pixel
        #pragma unroll 1
        for (int p = 0; p < 4; p++) {
            const int ty = oy4 + p;                   // tile row (<=29)
            const int gy = y0 + ty;
            if (gy < H_ && gx < W_) {
                const float* st = &sm.comb[ty + 2][ox + 2][1];
                const float* dl = &sm.del [ty + 1][ox + 1][0];
                float nv[16];
                #pragma unroll
                for (int j = 0; j < 8; j++) {
                    float z0, z1;
                    unpack2(acc[p][j], z0, z1);
                    float b0 = fminf(fmaxf(sigmoidf_(z0), 0.01f), 0.99f);
                    float b1 = fminf(fmaxf(sigmoidf_(z1), 0.01f), 0.99f);
                    nv[2 * j]     = b0 * st[2 * j]     + (1.f - b0) * dl[2 * j];
                    nv[2 * j + 1] = b1 * st[2 * j + 1] + (1.f - b1) * dl[2 * j + 1];
                }
                long pix = ((long)(b * H_ + gy)) * W_ + gx;
                sOut[pix * 4 + 0] = make_float4(nv[0],  nv[1],  nv[2],  nv[3]);
                sOut[pix * 4 + 1] = make_float4(nv[4],  nv[5],  nv[6],  nv[7]);
                sOut[pix * 4 + 2] = make_float4(nv[8],  nv[9],  nv[10], nv[11]);
                sOut[pix * 4 + 3] = make_float4(nv[12], nv[13], nv[14], nv[15]);
            }
        }
    }
}

extern "C" __global__ void zero_state() {
    long i = (long)blockIdx.x * blockDim.x + threadIdx.x;
    long n = (long)B_ * H_ * W_ * 4;
    if (i < n) g_state0[i] = make_float4(0.f, 0.f, 0.f, 0.f);
}

extern "C" __global__ void readout(const float4* __restrict__ s,
                                   const float* __restrict__ w_read,
                                   const float* __restrict__ b_read,
                                   float* __restrict__ out)
{
    long i = (long)blockIdx.x * blockDim.x + threadIdx.x;
    if (i >= (long)B_ * H_ * W_) return;
    float4 a0 = s[i * 4 + 0];
    float4 a1 = s[i * 4 + 1];
    float4 a2 = s[i * 4 + 2];
    float4 a3 = s[i * 4 + 3];
    float acc = b_read[0];
    acc += a0.x * w_read[0]  + a0.y * w_read[1]  + a0.z * w_read[2]  + a0.w * w_read[3];
    acc += a1.x * w_read[4]  + a1.y * w_read[5]  + a1.z * w_read[6]  + a1.w * w_read[7];
    acc += a2.x * w_read[8]  + a2.y * w_read[9]  + a2.z * w_read[10] + a2.w * w_read[11];
    acc += a3.x * w_read[12] + a3.y * w_read[13] + a3.z * w_read[14] + a3.w * w_read[15];
    out[i] = 1.0f / (1.0f + __expf(-acc));
}

extern "C" void kernel_launch(void* const* d_in, const int* in_sizes, int n_in,
                              void* d_out, int out_size)
{
    const float* x   = (const float*)d_in[0];
    const float* wp  = (const float*)d_in[1];
    const float* bp  = (const float*)d_in[2];
    const float* wu1 = (const float*)d_in[3];
    const float* bu1 = (const float*)d_in[4];
    const float* wu2 = (const float*)d_in[5];
    const float* bu2 = (const float*)d_in[6];
    const float* wt  = (const float*)d_in[7];
    const float* btc = (const float*)d_in[8];
    const float* bt  = (const float*)d_in[9];
    const float* wr  = (const float*)d_in[10];
    const float* br  = (const float*)d_in[11];
    float* out = (float*)d_out;

    cudaFuncSetAttribute(nca_step, cudaFuncAttributeMaxDynamicSharedMemorySize,
                         (int)sizeof(SM));

    float4 *s0, *s1;
    cudaGetSymbolAddress((void**)&s0, g_state0);
    cudaGetSymbolAddress((void**)&s1, g_state1);

    fuse_weights<<<10, 256>>>(wp, bp, wu1, bu1);

    long n4 = (long)B_ * H_ * W_ * 4;
    zero_state<<<(int)((n4 + 255) / 256), 256>>>();

    dim3 grid((W_ + TW - 1) / TW, (H_ + TH - 1) / TH, B_);
    float4* cur = s0;
    float4* nxt = s1;
    for (int s = 0; s < N_STEPS; s++) {
        nca_step<<<grid, NTHR, sizeof(SM)>>>(x, cur, nxt,
                                             wu2, bu2, wt, btc, bt);
        float4* t = cur; cur = nxt; nxt = t;
    }

    long npix = (long)B_ * H_ * W_;
    readout<<<(int)((npix + 255) / 256), 256>>>(cur, wr, br, out);
}

// round 11
// speedup vs baseline: 1.3308x; 1.3308x over previous
#include <cuda_runtime.h>

#define B_      32
#define H_      256
#define W_      256
#define TW      30          // output tile width
#define TH      30          // output tile height
#define RW      32          // stage-2 (delta) region = (TW+2)^2
#define CWD     34          // comb tile width  = TW+4
#define CHT     34          // comb tile height = TH+4
#define NTHR    256
#define N_STEPS 10

typedef unsigned long long u64;

// Ping-pong state, channels-last [B][H][W][16] as float4 x4
__device__ float4 g_state0[(size_t)B_ * H_ * W_ * 4];
__device__ float4 g_state1[(size_t)B_ * H_ * W_ * 4];
// Fused perceive->up1 weights: (W_up1 @ W_perceive): [16][17][9], bias [16]
__device__ float g_wf[16 * 17 * 9];
__device__ float g_bf[16];

__device__ __forceinline__ u64 pack2(float lo, float hi) {
    u64 r;
    asm("mov.b64 %0, {%1, %2};" : "=l"(r) : "f"(lo), "f"(hi));
    return r;
}
__device__ __forceinline__ void unpack2(u64 v, float& lo, float& hi) {
    asm("mov.b64 {%0, %1}, %2;" : "=f"(lo), "=f"(hi) : "l"(v));
}
__device__ __forceinline__ void fma2(u64& acc, u64 a, u64 b) {
    asm("fma.rn.f32x2 %0, %1, %2, %0;" : "+l"(acc) : "l"(a), "l"(b));
}
__device__ __forceinline__ float sigmoidf_(float z) {
    return 1.0f / (1.0f + __expf(-z));
}

struct SM {
    float comb[CHT][CWD][17];     // x + state, halo 2 (stride 17 conflict-free)
    float del [RW][RW][17];       // delta region, halo 1 (16 used, stride 17)
    ulonglong2 wf [17][9][4];     // fused conv 17->16 weights (out-ch quads)
    ulonglong2 wt [33][9][4];     // tau weights
    ulonglong2 wu2[16][4];        // up2
    u64 bf2[8];                   // fused bias pairs
    u64 bu22[8];
    u64 bt2[8];                   // b_tau_conv + b_tau
};

// ---- prep: fold up1 into perceive (both linear; relu is after up1) ----
extern "C" __global__ void fuse_weights(const float* __restrict__ wp,
                                        const float* __restrict__ bp,
                                        const float* __restrict__ w1,
                                        const float* __restrict__ b1)
{
    int i = blockIdx.x * blockDim.x + threadIdx.x;
    if (i < 16 * 153) {
        int o = i / 153, ck = i % 153;
        float s = 0.f;
        #pragma unroll
        for (int m = 0; m < 32; m++) s += w1[o * 32 + m] * wp[m * 153 + ck];
        g_wf[i] = s;
    }
    if (i < 16) {
        float s = b1[i];
        #pragma unroll
        for (int m = 0; m < 32; m++) s += w1[i * 32 + m] * bp[m];
        g_bf[i] = s;
    }
}

extern "C" __global__ void __launch_bounds__(NTHR, 1)
nca_step(const float*  __restrict__ x,
         const float4* __restrict__ sIn,
         float4*       __restrict__ sOut,
         const float* __restrict__ w_up2,  const float* __restrict__ b_up2,
         const float* __restrict__ w_tau,  const float* __restrict__ b_tauc,
         const float* __restrict__ b_tau)
{
    extern __shared__ char smraw[];
    SM& sm = *reinterpret_cast<SM*>(smraw);

    const int tid = threadIdx.x;
    const int x0 = blockIdx.x * TW;
    const int y0 = blockIdx.y * TH;
    const int b  = blockIdx.z;

    // ---- pack weights into shared ----
    for (int i = tid; i < 17 * 9 * 4; i += NTHR) {         // fused conv
        int q = i & 3, k = (i >> 2) % 9, c = i / 36;
        int o = 4 * q;
        sm.wf[c][k][q] = make_ulonglong2(
            pack2(g_wf[(o + 0) * 153 + c * 9 + k], g_wf[(o + 1) * 153 + c * 9 + k]),
            pack2(g_wf[(o + 2) * 153 + c * 9 + k], g_wf[(o + 3) * 153 + c * 9 + k]));
    }
    for (int i = tid; i < 33 * 9 * 4; i += NTHR) {         // tau
        int q = i & 3, k = (i >> 2) % 9, c = i / 36;
        int o = 4 * q;
        sm.wt[c][k][q] = make_ulonglong2(
            pack2(w_tau[(o + 0) * 297 + c * 9 + k], w_tau[(o + 1) * 297 + c * 9 + k]),
            pack2(w_tau[(o + 2) * 297 + c * 9 + k], w_tau[(o + 3) * 297 + c * 9 + k]));
    }
    for (int i = tid; i < 16 * 4; i += NTHR) {             // up2
        int q = i & 3, ci = i >> 2;
        int o = 4 * q;
        sm.wu2[ci][q] = make_ulonglong2(
            pack2(w_up2[(o + 0) * 16 + ci], w_up2[(o + 1) * 16 + ci]),
            pack2(w_up2[(o + 2) * 16 + ci], w_up2[(o + 3) * 16 + ci]));
    }
    if (tid < 8) {
        sm.bf2[tid] = pack2(g_bf[2 * tid], g_bf[2 * tid + 1]);
    } else if (tid < 16) {
        int j = tid - 8;
        sm.bu22[j] = pack2(b_up2[2 * j], b_up2[2 * j + 1]);
    } else if (tid < 24) {
        int j = tid - 16;
        sm.bt2[j] = pack2(b_tauc[2 * j] + b_tau[2 * j],
                          b_tauc[2 * j + 1] + b_tau[2 * j + 1]);
    }

    // ---- load combined = [x, state] tile with halo 2 (zero padded) ----
    for (int p = tid; p < CHT * CWD; p += NTHR) {
        int cy = p / CWD, cx = p % CWD;
        int gy = y0 - 2 + cy, gx = x0 - 2 + cx;
        float* dst = &sm.comb[cy][cx][0];
        if ((unsigned)gy < H_ && (unsigned)gx < W_) {
            long pix = ((long)(b * H_ + gy)) * W_ + gx;
            dst[0] = x[pix];
            float4 s0 = sIn[pix * 4 + 0];
            float4 s1 = sIn[pix * 4 + 1];
            float4 s2 = sIn[pix * 4 + 2];
            float4 s3 = sIn[pix * 4 + 3];
            dst[1] = s0.x;  dst[2] = s0.y;  dst[3] = s0.z;  dst[4] = s0.w;
            dst[5] = s1.x;  dst[6] = s1.y;  dst[7] = s1.z;  dst[8] = s1.w;
            dst[9] = s2.x;  dst[10] = s2.y; dst[11] = s2.z; dst[12] = s2.w;
            dst[13] = s3.x; dst[14] = s3.y; dst[15] = s3.z; dst[16] = s3.w;
        } else {
            #pragma unroll
            for (int c = 0; c < 17; c++) dst[c] = 0.f;
        }
    }
    __syncthreads();

    // ---- stage 2: fused conv(17->16)+relu+up2(16->16) over 32x32 region,
    //      4 vertical px / thread (256 thr = 32 cols x 8 groups, exact) ----
    {
        const int rx  = tid & 31;        // 0..31
        const int ry4 = (tid >> 5) << 2; // 0,4,...,28
        const int gx  = x0 - 1 + rx;
        const int gy0 = y0 - 1 + ry4;

        const float* cb = &sm.comb[ry4][rx][0];   // window top-left for px0

        u64 acc[4][8];
        #pragma unroll
        for (int p = 0; p < 4; p++)
            #pragma unroll
            for (int j = 0; j < 8; j++) acc[p][j] = sm.bf2[j];

        #pragma unroll 1
        for (int c = 0; c < 17; c++) {
            const float* cc = cb + c;
            float v[18];   // 6 rows x 3 cols
            #pragma unroll
            for (int i = 0; i < 6; i++)
                #pragma unroll
                for (int j = 0; j < 3; j++)
                    v[i * 3 + j] = cc[(i * CWD + j) * 17];
            #pragma unroll
            for (int k = 0; k < 9; k++) {
                const int dy = k / 3, dx = k % 3;
                u64 t0 = pack2(v[(dy + 0) * 3 + dx], v[(dy + 0) * 3 + dx]);
                u64 t1 = pack2(v[(dy + 1) * 3 + dx], v[(dy + 1) * 3 + dx]);
                u64 t2 = pack2(v[(dy + 2) * 3 + dx], v[(dy + 2) * 3 + dx]);
                u64 t3 = pack2(v[(dy + 3) * 3 + dx], v[(dy + 3) * 3 + dx]);
                #pragma unroll
                for (int q = 0; q < 4; q++) {
                    ulonglong2 w = sm.wf[c][k][q];
                    fma2(acc[0][2 * q],     w.x, t0);
                    fma2(acc[0][2 * q + 1], w.y, t0);
                    fma2(acc[1][2 * q],     w.x, t1);
                    fma2(acc[1][2 * q + 1], w.y, t1);
                    fma2(acc[2][2 * q],     w.x, t2);
                    fma2(acc[2][2 * q + 1], w.y, t2);
                    fma2(acc[3][2 * q],     w.x, t3);
                    fma2(acc[3][2 * q + 1], w.y, t3);
                }
            }
        }

        // relu + up2 + store delta to smem — FULLY UNROLLED over p so all
        // acc[] indices are compile-time constants (no local-mem demotion)
        #pragma unroll
        for (int p = 0; p < 4; p++) {
            float h[16];
            #pragma unroll
            for (int j = 0; j < 8; j++) {
                float a, bq;
                unpack2(acc[p][j], a, bq);
                h[2 * j]     = fmaxf(a, 0.f);
                h[2 * j + 1] = fmaxf(bq, 0.f);
            }
            u64 d[8];
            #pragma unroll
            for (int j = 0; j < 8; j++) d[j] = sm.bu22[j];
            #pragma unroll
            for (int ci = 0; ci < 16; ci++) {
                u64 pk = pack2(h[ci], h[ci]);
                #pragma unroll
                for (int q = 0; q < 4; q++) {
                    ulonglong2 w = sm.wu2[ci][q];
                    fma2(d[2 * q],     w.x, pk);
                    fma2(d[2 * q + 1], w.y, pk);
                }
            }
            const bool vp = (unsigned)gx < W_ && (unsigned)(gy0 + p) < H_;
            float* dd = &sm.del[ry4 + p][rx][0];
            #pragma unroll
            for (int j = 0; j < 8; j++) {
                float e0, e1;
                unpack2(d[j], e0, e1);
                dd[2 * j]     = vp ? e0 : 0.f;
                dd[2 * j + 1] = vp ? e1 : 0.f;
            }
        }
    }
    __syncthreads();

    // ---- stage 3: tau conv3x3 (33->16) + gated blend, 4 vertical px/thread
    //      (240 threads = 30 cols x 8 groups, clamped; dup rows idempotent) ----
    if (tid < 240) {
        const int ox  = tid % 30;
        const int g   = tid / 30;                    // 0..7
        const int oy4 = (4 * g < 26) ? 4 * g : 26;   // 0,4,...,24,26
        const int gx  = x0 + ox;

        const float* cb = &sm.comb[oy4 + 1][ox + 1][0];   // comb window base
        const float* db = &sm.del [oy4][ox][0];           // del window base

        u64 acc[4][8];
        #pragma unroll
        for (int p = 0; p < 4; p++)
            #pragma unroll
            for (int j = 0; j < 8; j++) acc[p][j] = sm.bt2[j];

        #pragma unroll 1
        for (int c = 0; c < 17; c++) {   // x + state channels from comb
            const float* cc = cb + c;
            float v[18];
            #pragma unroll
            for (int i = 0; i < 6; i++)
                #pragma unroll
                for (int j = 0; j < 3; j++)
                    v[i * 3 + j] = cc[(i * CWD + j) * 17];
            #pragma unroll
            for (int k = 0; k < 9; k++) {
                const int dy = k / 3, dx = k % 3;
                u64 t0 = pack2(v[(dy + 0) * 3 + dx], v[(dy + 0) * 3 + dx]);
                u64 t1 = pack2(v[(dy + 1) * 3 + dx], v[(dy + 1) * 3 + dx]);
                u64 t2 = pack2(v[(dy + 2) * 3 + dx], v[(dy + 2) * 3 + dx]);
                u64 t3 = pack2(v[(dy + 3) * 3 + dx], v[(dy + 3) * 3 + dx]);
                #pragma unroll
                for (int q = 0; q < 4; q++) {
                    ulonglong2 w = sm.wt[c][k][q];
                    fma2(acc[0][2 * q],     w.x, t0);
                    fma2(acc[0][2 * q + 1], w.y, t0);
                    fma2(acc[1][2 * q],     w.x, t1);
                    fma2(acc[1][2 * q + 1], w.y, t1);
                    fma2(acc[2][2 * q],     w.x, t2);
                    fma2(acc[2][2 * q + 1], w.y, t2);
                    fma2(acc[3][2 * q],     w.x, t3);
                    fma2(acc[3][2 * q + 1], w.y, t3);
                }
            }
        }
        #pragma unroll 1
        for (int c = 0; c < 16; c++) {   // delta channels from del
            const float* cc = db + c;
            float v[18];
            #pragma unroll
            for (int i = 0; i < 6; i++)
                #pragma unroll
                for (int j = 0; j < 3; j++)
                    v[i * 3 + j] = cc[(i * RW + j) * 17];
            #pragma unroll
            for (int k = 0; k < 9; k++) {
                const int dy = k / 3, dx = k % 3;
                u64 t0 = pack2(v[(dy + 0) * 3 + dx], v[(dy + 0) * 3 + dx]);
                u64 t1 = pack2(v[(dy + 1) * 3 + dx], v[(dy + 1) * 3 + dx]);
                u64 t2 = pack2(v[(dy + 2) * 3 + dx], v[(dy + 2) * 3 + dx]);
                u64 t3 = pack2(v[(dy + 3) * 3 + dx], v[(dy + 3) * 3 + dx]);
                #pragma unroll
                for (int q = 0; q < 4; q++) {
                    ulonglong2 w = sm.wt[17 + c][k][q];
                    fma2(acc[0][2 * q],     w.x, t0);
                    fma2(acc[0][2 * q + 1], w.y, t0);
                    fma2(acc[1][2 * q],     w.x, t1);
                    fma2(acc[1][2 * q + 1], w.y, t1);
                    fma2(acc[2][2 * q],     w.x, t2);
                    fma2(acc[2][2 * q + 1], w.y, t2);
                    fma2(acc[3][2 * q],     w.x, t3);
                    fma2(acc[3][2 * q + 1], w.y, t3);
                }
            }
        }

        // sigmoid gate + blend + store — FULLY UNROLLED over p
        #pragma unroll
        for (int p = 0; p < 4; p++) {
            const int ty = oy4 + p;                   // tile row (<=29)
            const int gy = y0 + ty;
            if (gy < H_ && gx < W_) {
                const float* st = &sm.comb[ty + 2][ox + 2][1];
                const float* dl = &sm.del [ty + 1][ox + 1][0];
                float nv[16];
                #pragma unroll
                for (int j = 0; j < 8; j++) {
                    float z0, z1;
                    unpack2(acc[p][j], z0, z1);
                    float b0 = fminf(fmaxf(sigmoidf_(z0), 0.01f), 0.99f);
                    float b1 = fminf(fmaxf(sigmoidf_(z1), 0.01f), 0.99f);
                    nv[2 * j]     = b0 * st[2 * j]     + (1.f - b0) * dl[2 * j];
                    nv[2 * j + 1] = b1 * st[2 * j + 1] + (1.f - b1) * dl[2 * j + 1];
                }
                long pix = ((long)(b * H_ + gy)) * W_ + gx;
                sOut[pix * 4 + 0] = make_float4(nv[0],  nv[1],  nv[2],  nv[3]);
                sOut[pix * 4 + 1] = make_float4(nv[4],  nv[5],  nv[6],  nv[7]);
                sOut[pix * 4 + 2] = make_float4(nv[8],  nv[9],  nv[10], nv[11]);
                sOut[pix * 4 + 3] = make_float4(nv[12], nv[13], nv[14], nv[15]);
            }
        }
    }
}

extern "C" __global__ void zero_state() {
    long i = (long)blockIdx.x * blockDim.x + threadIdx.x;
    long n = (long)B_ * H_ * W_ * 4;
    if (i < n) g_state0[i] = make_float4(0.f, 0.f, 0.f, 0.f);
}

extern "C" __global__ void readout(const float4* __restrict__ s,
                                   const float* __restrict__ w_read,
                                   const float* __restrict__ b_read,
                                   float* __restrict__ out)
{
    long i = (long)blockIdx.x * blockDim.x + threadIdx.x;
    if (i >= (long)B_ * H_ * W_) return;
    float4 a0 = s[i * 4 + 0];
    float4 a1 = s[i * 4 + 1];
    float4 a2 = s[i * 4 + 2];
    float4 a3 = s[i * 4 + 3];
    float acc = b_read[0];
    acc += a0.x * w_read[0]  + a0.y * w_read[1]  + a0.z * w_read[2]  + a0.w * w_read[3];
    acc += a1.x * w_read[4]  + a1.y * w_read[5]  + a1.z * w_read[6]  + a1.w * w_read[7];
    acc += a2.x * w_read[8]  + a2.y * w_read[9]  + a2.z * w_read[10] + a2.w * w_read[11];
    acc += a3.x * w_read[12] + a3.y * w_read[13] + a3.z * w_read[14] + a3.w * w_read[15];
    out[i] = 1.0f / (1.0f + __expf(-acc));
}

extern "C" void kernel_launch(void* const* d_in, const int* in_sizes, int n_in,
                              void* d_out, int out_size)
{
    const float* x   = (const float*)d_in[0];
    const float* wp  = (const float*)d_in[1];
    const float* bp  = (const float*)d_in[2];
    const float* wu1 = (const float*)d_in[3];
    const float* bu1 = (const float*)d_in[4];
    const float* wu2 = (const float*)d_in[5];
    const float* bu2 = (const float*)d_in[6];
    const float* wt  = (const float*)d_in[7];
    const float* btc = (const float*)d_in[8];
    const float* bt  = (const float*)d_in[9];
    const float* wr  = (const float*)d_in[10];
    const float* br  = (const float*)d_in[11];
    float* out = (float*)d_out;

    cudaFuncSetAttribute(nca_step, cudaFuncAttributeMaxDynamicSharedMemorySize,
                         (int)sizeof(SM));

    float4 *s0, *s1;
    cudaGetSymbolAddress((void**)&s0, g_state0);
    cudaGetSymbolAddress((void**)&s1, g_state1);

    fuse_weights<<<10, 256>>>(wp, bp, wu1, bu1);

    long n4 = (long)B_ * H_ * W_ * 4;
    zero_state<<<(int)((n4 + 255) / 256), 256>>>();

    dim3 grid((W_ + TW - 1) / TW, (H_ + TH - 1) / TH, B_);
    float4* cur = s0;
    float4* nxt = s1;
    for (int s = 0; s < N_STEPS; s++) {
        nca_step<<<grid, NTHR, sizeof(SM)>>>(x, cur, nxt,
                                             wu2, bu2, wt, btc, bt);
        float4* t = cur; cur = nxt; nxt = t;
    }

    long npix = (long)B_ * H_ * W_;
    readout<<<(int)((npix + 255) / 256), 256>>>(cur, wr, br, out);
}

// round 12
// speedup vs baseline: 1.5037x; 1.1299x over previous
#include <cuda_runtime.h>

#define B_      32
#define H_      256
#define W_      256
#define TW      30          // output tile width
#define TH      34          // output tile height
#define RW      32          // stage-2 region cols = TW+2
#define RH      36          // stage-2 region rows = TH+2 (= 12 groups of 3, exact)
#define CWD     34          // comb tile width  = TW+4
#define CHT     38          // comb tile height = TH+4
#define NTHR    384
#define N_STEPS 10

typedef unsigned long long u64;

// Ping-pong state, channels-last [B][H][W][16] as float4 x4
__device__ float4 g_state0[(size_t)B_ * H_ * W_ * 4];
__device__ float4 g_state1[(size_t)B_ * H_ * W_ * 4];
// Fused perceive->up1 weights: (W_up1 @ W_perceive): [16][17][9], bias [16]
__device__ float g_wf[16 * 17 * 9];
__device__ float g_bf[16];

__device__ __forceinline__ u64 pack2(float lo, float hi) {
    u64 r;
    asm("mov.b64 %0, {%1, %2};" : "=l"(r) : "f"(lo), "f"(hi));
    return r;
}
__device__ __forceinline__ void unpack2(u64 v, float& lo, float& hi) {
    asm("mov.b64 {%0, %1}, %2;" : "=f"(lo), "=f"(hi) : "l"(v));
}
__device__ __forceinline__ void fma2(u64& acc, u64 a, u64 b) {
    asm("fma.rn.f32x2 %0, %1, %2, %0;" : "+l"(acc) : "l"(a), "l"(b));
}
__device__ __forceinline__ float sigmoidf_(float z) {
    return 1.0f / (1.0f + __expf(-z));
}

struct SM {
    float comb[CHT][CWD][17];     // x + state, halo 2 (stride 17 conflict-free)
    float del [RH][RW][17];       // delta, halo 1 (16 used, stride 17)
    ulonglong2 wf [17][9][4];     // fused conv 17->16 weights (out-ch quads)
    ulonglong2 wt [33][9][4];     // tau weights
    ulonglong2 wu2[16][4];        // up2
    u64 bf2[8];                   // fused bias pairs
    u64 bu22[8];
    u64 bt2[8];                   // b_tau_conv + b_tau
};

// ---- prep: fold up1 into perceive (both linear; relu is after up1) ----
extern "C" __global__ void fuse_weights(const float* __restrict__ wp,
                                        const float* __restrict__ bp,
                                        const float* __restrict__ w1,
                                        const float* __restrict__ b1)
{
    int i = blockIdx.x * blockDim.x + threadIdx.x;
    if (i < 16 * 153) {
        int o = i / 153, ck = i % 153;
        float s = 0.f;
        #pragma unroll
        for (int m = 0; m < 32; m++) s += w1[o * 32 + m] * wp[m * 153 + ck];
        g_wf[i] = s;
    }
    if (i < 16) {
        float s = b1[i];
        #pragma unroll
        for (int m = 0; m < 32; m++) s += w1[i * 32 + m] * bp[m];
        g_bf[i] = s;
    }
}

extern "C" __global__ void __launch_bounds__(NTHR, 1)
nca_step(const float*  __restrict__ x,
         const float4* __restrict__ sIn,
         float4*       __restrict__ sOut,
         const float* __restrict__ w_up2,  const float* __restrict__ b_up2,
         const float* __restrict__ w_tau,  const float* __restrict__ b_tauc,
         const float* __restrict__ b_tau)
{
    extern __shared__ char smraw[];
    SM& sm = *reinterpret_cast<SM*>(smraw);

    const int tid = threadIdx.x;
    const int x0 = blockIdx.x * TW;
    const int y0 = blockIdx.y * TH;
    const int b  = blockIdx.z;

    // ---- pack weights into shared ----
    for (int i = tid; i < 17 * 9 * 4; i += NTHR) {         // fused conv
        int q = i & 3, k = (i >> 2) % 9, c = i / 36;
        int o = 4 * q;
        sm.wf[c][k][q] = make_ulonglong2(
            pack2(g_wf[(o + 0) * 153 + c * 9 + k], g_wf[(o + 1) * 153 + c * 9 + k]),
            pack2(g_wf[(o + 2) * 153 + c * 9 + k], g_wf[(o + 3) * 153 + c * 9 + k]));
    }
    for (int i = tid; i < 33 * 9 * 4; i += NTHR) {         // tau
        int q = i & 3, k = (i >> 2) % 9, c = i / 36;
        int o = 4 * q;
        sm.wt[c][k][q] = make_ulonglong2(
            pack2(w_tau[(o + 0) * 297 + c * 9 + k], w_tau[(o + 1) * 297 + c * 9 + k]),
            pack2(w_tau[(o + 2) * 297 + c * 9 + k], w_tau[(o + 3) * 297 + c * 9 + k]));
    }
    for (int i = tid; i < 16 * 4; i += NTHR) {             // up2
        int q = i & 3, ci = i >> 2;
        int o = 4 * q;
        sm.wu2[ci][q] = make_ulonglong2(
            pack2(w_up2[(o + 0) * 16 + ci], w_up2[(o + 1) * 16 + ci]),
            pack2(w_up2[(o + 2) * 16 + ci], w_up2[(o + 3) * 16 + ci]));
    }
    if (tid < 8) {
        sm.bf2[tid] = pack2(g_bf[2 * tid], g_bf[2 * tid + 1]);
    } else if (tid < 16) {
        int j = tid - 8;
        sm.bu22[j] = pack2(b_up2[2 * j], b_up2[2 * j + 1]);
    } else if (tid < 24) {
        int j = tid - 16;
        sm.bt2[j] = pack2(b_tauc[2 * j] + b_tau[2 * j],
                          b_tauc[2 * j + 1] + b_tau[2 * j + 1]);
    }

    // ---- load combined = [x, state] tile with halo 2 (zero padded) ----
    for (int p = tid; p < CHT * CWD; p += NTHR) {
        int cy = p / CWD, cx = p % CWD;
        int gy = y0 - 2 + cy, gx = x0 - 2 + cx;
        float* dst = &sm.comb[cy][cx][0];
        if ((unsigned)gy < H_ && (unsigned)gx < W_) {
            long pix = ((long)(b * H_ + gy)) * W_ + gx;
            dst[0] = x[pix];
            float4 s0 = sIn[pix * 4 + 0];
            float4 s1 = sIn[pix * 4 + 1];
            float4 s2 = sIn[pix * 4 + 2];
            float4 s3 = sIn[pix * 4 + 3];
            dst[1] = s0.x;  dst[2] = s0.y;  dst[3] = s0.z;  dst[4] = s0.w;
            dst[5] = s1.x;  dst[6] = s1.y;  dst[7] = s1.z;  dst[8] = s1.w;
            dst[9] = s2.x;  dst[10] = s2.y; dst[11] = s2.z; dst[12] = s2.w;
            dst[13] = s3.x; dst[14] = s3.y; dst[15] = s3.z; dst[16] = s3.w;
        } else {
            #pragma unroll
            for (int c = 0; c < 17; c++) dst[c] = 0.f;
        }
    }
    __syncthreads();

    // ---- stage 2: fused conv(17->16)+relu+up2(16->16) over 32x36 region,
    //      3 vertical px / thread (384 thr = 32 cols x 12 groups, EXACT) ----
    {
        const int rx  = tid & 31;        // 0..31
        const int ry3 = 3 * (tid >> 5);  // 0,3,...,33  (12 groups, no clamp)
        const int gx  = x0 - 1 + rx;
        const int gy0 = y0 - 1 + ry3;

        const float* cb = &sm.comb[ry3][rx][0];   // window top-left for px0

        u64 acc[3][8];
        #pragma unroll
        for (int p = 0; p < 3; p++)
            #pragma unroll
            for (int j = 0; j < 8; j++) acc[p][j] = sm.bf2[j];

        #pragma unroll 1
        for (int c = 0; c < 17; c++) {
            const float* cc = cb + c;
            float v[15];   // 5 rows x 3 cols
            #pragma unroll
            for (int i = 0; i < 5; i++)
                #pragma unroll
                for (int j = 0; j < 3; j++)
                    v[i * 3 + j] = cc[(i * CWD + j) * 17];
            #pragma unroll
            for (int k = 0; k < 9; k++) {
                const int dy = k / 3, dx = k % 3;
                u64 t0 = pack2(v[(dy + 0) * 3 + dx], v[(dy + 0) * 3 + dx]);
                u64 t1 = pack2(v[(dy + 1) * 3 + dx], v[(dy + 1) * 3 + dx]);
                u64 t2 = pack2(v[(dy + 2) * 3 + dx], v[(dy + 2) * 3 + dx]);
                #pragma unroll
                for (int q = 0; q < 4; q++) {
                    ulonglong2 w = sm.wf[c][k][q];
                    fma2(acc[0][2 * q],     w.x, t0);
                    fma2(acc[0][2 * q + 1], w.y, t0);
                    fma2(acc[1][2 * q],     w.x, t1);
                    fma2(acc[1][2 * q + 1], w.y, t1);
                    fma2(acc[2][2 * q],     w.x, t2);
                    fma2(acc[2][2 * q + 1], w.y, t2);
                }
            }
        }

        // relu
        float h[3][16];
        #pragma unroll
        for (int p = 0; p < 3; p++)
            #pragma unroll
            for (int j = 0; j < 8; j++) {
                float a, bq;
                unpack2(acc[p][j], a, bq);
                h[p][2 * j]     = fmaxf(a, 0.f);
                h[p][2 * j + 1] = fmaxf(bq, 0.f);
            }

        // up2: 1x1 16 -> 16 = delta (3 pixels share weight loads)
        u64 d[3][8];
        #pragma unroll
        for (int p = 0; p < 3; p++)
            #pragma unroll
            for (int j = 0; j < 8; j++) d[p][j] = sm.bu22[j];
        #pragma unroll
        for (int ci = 0; ci < 16; ci++) {
            u64 p0 = pack2(h[0][ci], h[0][ci]);
            u64 p1 = pack2(h[1][ci], h[1][ci]);
            u64 p2 = pack2(h[2][ci], h[2][ci]);
            #pragma unroll
            for (int q = 0; q < 4; q++) {
                ulonglong2 w = sm.wu2[ci][q];
                fma2(d[0][2 * q],     w.x, p0);
                fma2(d[0][2 * q + 1], w.y, p0);
                fma2(d[1][2 * q],     w.x, p1);
                fma2(d[1][2 * q + 1], w.y, p1);
                fma2(d[2][2 * q],     w.x, p2);
                fma2(d[2][2 * q + 1], w.y, p2);
            }
        }
        #pragma unroll
        for (int p = 0; p < 3; p++) {
            const bool vp = (unsigned)gx < W_ && (unsigned)(gy0 + p) < H_;
            float* dd = &sm.del[ry3 + p][rx][0];
            #pragma unroll
            for (int j = 0; j < 8; j++) {
                float e0, e1;
                unpack2(d[p][j], e0, e1);
                dd[2 * j]     = vp ? e0 : 0.f;
                dd[2 * j + 1] = vp ? e1 : 0.f;
            }
        }
    }
    __syncthreads();

    // ---- stage 3: tau conv3x3 (33->16) + gated blend, 3 vertical px/thread
    //      (360 threads = 30 cols x 12 groups, clamped to 34 rows) ----
    if (tid < 360) {
        const int ox  = tid % 30;
        const int g   = tid / 30;                    // 0..11
        const int oy3 = (3 * g < TH - 3) ? 3 * g : TH - 3;   // 0,3,...,30,31
        const int gx  = x0 + ox;

        const float* cb = &sm.comb[oy3 + 1][ox + 1][0];   // comb window base
        const float* db = &sm.del [oy3][ox][0];           // del window base

        u64 acc[3][8];
        #pragma unroll
        for (int p = 0; p < 3; p++)
            #pragma unroll
            for (int j = 0; j < 8; j++) acc[p][j] = sm.bt2[j];

        #pragma unroll 1
        for (int c = 0; c < 17; c++) {   // x + state channels from comb
            const float* cc = cb + c;
            float v[15];
            #pragma unroll
            for (int i = 0; i < 5; i++)
                #pragma unroll
                for (int j = 0; j < 3; j++)
                    v[i * 3 + j] = cc[(i * CWD + j) * 17];
            #pragma unroll
            for (int k = 0; k < 9; k++) {
                const int dy = k / 3, dx = k % 3;
                u64 t0 = pack2(v[(dy + 0) * 3 + dx], v[(dy + 0) * 3 + dx]);
                u64 t1 = pack2(v[(dy + 1) * 3 + dx], v[(dy + 1) * 3 + dx]);
                u64 t2 = pack2(v[(dy + 2) * 3 + dx], v[(dy + 2) * 3 + dx]);
                #pragma unroll
                for (int q = 0; q < 4; q++) {
                    ulonglong2 w = sm.wt[c][k][q];
                    fma2(acc[0][2 * q],     w.x, t0);
                    fma2(acc[0][2 * q + 1], w.y, t0);
                    fma2(acc[1][2 * q],     w.x, t1);
                    fma2(acc[1][2 * q + 1], w.y, t1);
                    fma2(acc[2][2 * q],     w.x, t2);
                    fma2(acc[2][2 * q + 1], w.y, t2);
                }
            }
        }
        #pragma unroll 1
        for (int c = 0; c < 16; c++) {   // delta channels from del
            const float* cc = db + c;
            float v[15];
            #pragma unroll
            for (int i = 0; i < 5; i++)
                #pragma unroll
                for (int j = 0; j < 3; j++)
                    v[i * 3 + j] = cc[(i * RW + j) * 17];
            #pragma unroll
            for (int k = 0; k < 9; k++) {
                const int dy = k / 3, dx = k % 3;
                u64 t0 = pack2(v[(dy + 0) * 3 + dx], v[(dy + 0) * 3 + dx]);
                u64 t1 = pack2(v[(dy + 1) * 3 + dx], v[(dy + 1) * 3 + dx]);
                u64 t2 = pack2(v[(dy + 2) * 3 + dx], v[(dy + 2) * 3 + dx]);
                #pragma unroll
                for (int q = 0; q < 4; q++) {
                    ulonglong2 w = sm.wt[17 + c][k][q];
                    fma2(acc[0][2 * q],     w.x, t0);
                    fma2(acc[0][2 * q + 1], w.y, t0);
                    fma2(acc[1][2 * q],     w.x, t1);
                    fma2(acc[1][2 * q + 1], w.y, t1);
                    fma2(acc[2][2 * q],     w.x, t2);
                    fma2(acc[2][2 * q + 1], w.y, t2);
                }
            }
        }

        // sigmoid gate + blend + store per pixel
        #pragma unroll
        for (int p = 0; p < 3; p++) {
            const int ty = oy3 + p;                   // tile row (<=33)
            const int gy = y0 + ty;
            if (gy < H_ && gx < W_) {
                const float* st = &sm.comb[ty + 2][ox + 2][1];
                const float* dl = &sm.del [ty + 1][ox + 1][0];
                float nv[16];
                #pragma unroll
                for (int j = 0; j < 8; j++) {
                    float z0, z1;
                    unpack2(acc[p][j], z0, z1);
                    float b0 = fminf(fmaxf(sigmoidf_(z0), 0.01f), 0.99f);
                    float b1 = fminf(fmaxf(sigmoidf_(z1), 0.01f), 0.99f);
                    nv[2 * j]     = b0 * st[2 * j]     + (1.f - b0) * dl[2 * j];
                    nv[2 * j + 1] = b1 * st[2 * j + 1] + (1.f - b1) * dl[2 * j + 1];
                }
                long pix = ((long)(b * H_ + gy)) * W_ + gx;
                sOut[pix * 4 + 0] = make_float4(nv[0],  nv[1],  nv[2],  nv[3]);
                sOut[pix * 4 + 1] = make_float4(nv[4],  nv[5],  nv[6],  nv[7]);
                sOut[pix * 4 + 2] = make_float4(nv[8],  nv[9],  nv[10], nv[11]);
                sOut[pix * 4 + 3] = make_float4(nv[12], nv[13], nv[14], nv[15]);
            }
        }
    }
}

extern "C" __global__ void zero_state() {
    long i = (long)blockIdx.x * blockDim.x + threadIdx.x;
    long n = (long)B_ * H_ * W_ * 4;
    if (i < n) g_state0[i] = make_float4(0.f, 0.f, 0.f, 0.f);
}

extern "C" __global__ void readout(const float4* __restrict__ s,
                                   const float* __restrict__ w_read,
                                   const float* __restrict__ b_read,
                                   float* __restrict__ out)
{
    long i = (long)blockIdx.x * blockDim.x + threadIdx.x;
    if (i >= (long)B_ * H_ * W_) return;
    float4 a0 = s[i * 4 + 0];
    float4 a1 = s[i * 4 + 1];
    float4 a2 = s[i * 4 + 2];
    float4 a3 = s[i * 4 + 3];
    float acc = b_read[0];
    acc += a0.x * w_read[0]  + a0.y * w_read[1]  + a0.z * w_read[2]  + a0.w * w_read[3];
    acc += a1.x * w_read[4]  + a1.y * w_read[5]  + a1.z * w_read[6]  + a1.w * w_read[7];
    acc += a2.x * w_read[8]  + a2.y * w_read[9]  + a2.z * w_read[10] + a2.w * w_read[11];
    acc += a3.x * w_read[12] + a3.y * w_read[13] + a3.z * w_read[14] + a3.w * w_read[15];
    out[i] = 1.0f / (1.0f + __expf(-acc));
}

extern "C" void kernel_launch(void* const* d_in, const int* in_sizes, int n_in,
                              void* d_out, int out_size)
{
    const float* x   = (const float*)d_in[0];
    const float* wp  = (const float*)d_in[1];
    const float* bp  = (const float*)d_in[2];
    const float* wu1 = (const float*)d_in[3];
    const float* bu1 = (const float*)d_in[4];
    const float* wu2 = (const float*)d_in[5];
    const float* bu2 = (const float*)d_in[6];
    const float* wt  = (const float*)d_in[7];
    const float* btc = (const float*)d_in[8];
    const float* bt  = (const float*)d_in[9];
    const float* wr  = (const float*)d_in[10];
    const float* br  = (const float*)d_in[11];
    float* out = (float*)d_out;

    cudaFuncSetAttribute(nca_step, cudaFuncAttributeMaxDynamicSharedMemorySize,
                         (int)sizeof(SM));

    float4 *s0, *s1;
    cudaGetSymbolAddress((void**)&s0, g_state0);
    cudaGetSymbolAddress((void**)&s1, g_state1);

    fuse_weights<<<10, 256>>>(wp, bp, wu1, bu1);

    long n4 = (long)B_ * H_ * W_ * 4;
    zero_state<<<(int)((n4 + 255) / 256), 256>>>();

    dim3 grid((W_ + TW - 1) / TW, (H_ + TH - 1) / TH, B_);
    float4* cur = s0;
    float4* nxt = s1;
    for (int s = 0; s < N_STEPS; s++) {
        nca_step<<<grid, NTHR, sizeof(SM)>>>(x, cur, nxt,
                                             wu2, bu2, wt, btc, bt);
        float4* t = cur; cur = nxt; nxt = t;
    }

    long npix = (long)B_ * H_ * W_;
    readout<<<(int)((npix + 255) / 256), 256>>>(cur, wr, br, out);
}

// round 13
// speedup vs baseline: 1.5080x; 1.0029x over previous
#include <cuda_runtime.h>

#define B_      32
#define H_      256
#define W_      256
#define TW      30          // output tile width
#define TH      34          // output tile height
#define RW      32          // stage-2 region cols = TW+2
#define RH      36          // stage-2 region rows = TH+2 (= 12 groups of 3, exact)
#define CWD     34          // comb tile width  = TW+4
#define CHT     38          // comb tile height = TH+4
#define NTHR    384
#define N_STEPS 10

typedef unsigned long long u64;

// Ping-pong state, channels-last [B][H][W][16] as float4 x4
__device__ float4 g_state0[(size_t)B_ * H_ * W_ * 4];
__device__ float4 g_state1[(size_t)B_ * H_ * W_ * 4];
// Fused perceive->up1 weights: (W_up1 @ W_perceive): [16][17][9], bias [16]
__device__ float g_wf[16 * 17 * 9];
__device__ float g_bf[16];

__device__ __forceinline__ u64 pack2(float lo, float hi) {
    u64 r;
    asm("mov.b64 %0, {%1, %2};" : "=l"(r) : "f"(lo), "f"(hi));
    return r;
}
__device__ __forceinline__ void unpack2(u64 v, float& lo, float& hi) {
    asm("mov.b64 {%0, %1}, %2;" : "=f"(lo), "=f"(hi) : "l"(v));
}
__device__ __forceinline__ void fma2(u64& acc, u64 a, u64 b) {
    asm("fma.rn.f32x2 %0, %1, %2, %0;" : "+l"(acc) : "l"(a), "l"(b));
}
__device__ __forceinline__ float sigmoidf_(float z) {
    return 1.0f / (1.0f + __expf(-z));
}

struct SM {
    float comb[CHT][CWD][17];     // x + state, halo 2 (stride 17 conflict-free)
    float del [RH][RW][17];       // delta, halo 1 (16 used, stride 17)
    ulonglong2 wf [17][9][4];     // fused conv 17->16 weights (out-ch quads)
    ulonglong2 wt [33][9][4];     // tau weights
    ulonglong2 wu2[16][4];        // up2
    u64 bf2[8];                   // fused bias pairs
    u64 bu22[8];
    u64 bt2[8];                   // b_tau_conv + b_tau
};

// ---- prep: fold up1 into perceive (both linear; relu is after up1) ----
extern "C" __global__ void fuse_weights(const float* __restrict__ wp,
                                        const float* __restrict__ bp,
                                        const float* __restrict__ w1,
                                        const float* __restrict__ b1)
{
    int i = blockIdx.x * blockDim.x + threadIdx.x;
    if (i < 16 * 153) {
        int o = i / 153, ck = i % 153;
        float s = 0.f;
        #pragma unroll
        for (int m = 0; m < 32; m++) s += w1[o * 32 + m] * wp[m * 153 + ck];
        g_wf[i] = s;
    }
    if (i < 16) {
        float s = b1[i];
        #pragma unroll
        for (int m = 0; m < 32; m++) s += w1[i * 32 + m] * bp[m];
        g_bf[i] = s;
    }
}

extern "C" __global__ void __launch_bounds__(NTHR, 1)
nca_step(const float*  __restrict__ x,
         const float4* __restrict__ sIn,
         float4*       __restrict__ sOut,
         const float* __restrict__ w_up2,  const float* __restrict__ b_up2,
         const float* __restrict__ w_tau,  const float* __restrict__ b_tauc,
         const float* __restrict__ b_tau)
{
    extern __shared__ char smraw[];
    SM& sm = *reinterpret_cast<SM*>(smraw);

    const int tid = threadIdx.x;
    const int x0 = blockIdx.x * TW;
    const int y0 = blockIdx.y * TH;
    const int b  = blockIdx.z;

    // ---- pack weights into shared ----
    for (int i = tid; i < 17 * 9 * 4; i += NTHR) {         // fused conv
        int q = i & 3, k = (i >> 2) % 9, c = i / 36;
        int o = 4 * q;
        sm.wf[c][k][q] = make_ulonglong2(
            pack2(g_wf[(o + 0) * 153 + c * 9 + k], g_wf[(o + 1) * 153 + c * 9 + k]),
            pack2(g_wf[(o + 2) * 153 + c * 9 + k], g_wf[(o + 3) * 153 + c * 9 + k]));
    }
    for (int i = tid; i < 33 * 9 * 4; i += NTHR) {         // tau
        int q = i & 3, k = (i >> 2) % 9, c = i / 36;
        int o = 4 * q;
        sm.wt[c][k][q] = make_ulonglong2(
            pack2(w_tau[(o + 0) * 297 + c * 9 + k], w_tau[(o + 1) * 297 + c * 9 + k]),
            pack2(w_tau[(o + 2) * 297 + c * 9 + k], w_tau[(o + 3) * 297 + c * 9 + k]));
    }
    for (int i = tid; i < 16 * 4; i += NTHR) {             // up2
        int q = i & 3, ci = i >> 2;
        int o = 4 * q;
        sm.wu2[ci][q] = make_ulonglong2(
            pack2(w_up2[(o + 0) * 16 + ci], w_up2[(o + 1) * 16 + ci]),
            pack2(w_up2[(o + 2) * 16 + ci], w_up2[(o + 3) * 16 + ci]));
    }
    if (tid < 8) {
        sm.bf2[tid] = pack2(g_bf[2 * tid], g_bf[2 * tid + 1]);
    } else if (tid < 16) {
        int j = tid - 8;
        sm.bu22[j] = pack2(b_up2[2 * j], b_up2[2 * j + 1]);
    } else if (tid < 24) {
        int j = tid - 16;
        sm.bt2[j] = pack2(b_tauc[2 * j] + b_tau[2 * j],
                          b_tauc[2 * j + 1] + b_tau[2 * j + 1]);
    }

    // ---- load combined = [x, state] tile with halo 2 (zero padded) ----
    for (int p = tid; p < CHT * CWD; p += NTHR) {
        int cy = p / CWD, cx = p % CWD;
        int gy = y0 - 2 + cy, gx = x0 - 2 + cx;
        float* dst = &sm.comb[cy][cx][0];
        if ((unsigned)gy < H_ && (unsigned)gx < W_) {
            long pix = ((long)(b * H_ + gy)) * W_ + gx;
            dst[0] = x[pix];
            float4 s0 = sIn[pix * 4 + 0];
            float4 s1 = sIn[pix * 4 + 1];
            float4 s2 = sIn[pix * 4 + 2];
            float4 s3 = sIn[pix * 4 + 3];
            dst[1] = s0.x;  dst[2] = s0.y;  dst[3] = s0.z;  dst[4] = s0.w;
            dst[5] = s1.x;  dst[6] = s1.y;  dst[7] = s1.z;  dst[8] = s1.w;
            dst[9] = s2.x;  dst[10] = s2.y; dst[11] = s2.z; dst[12] = s2.w;
            dst[13] = s3.x; dst[14] = s3.y; dst[15] = s3.z; dst[16] = s3.w;
        } else {
            #pragma unroll
            for (int c = 0; c < 17; c++) dst[c] = 0.f;
        }
    }
    __syncthreads();

    // ---- stage 2: fused conv(17->16)+relu+up2(16->16) over 32x36 region,
    //      3 vertical px / thread (384 thr = 32 cols x 12 groups, EXACT) ----
    {
        const int rx  = tid & 31;        // 0..31
        const int ry3 = 3 * (tid >> 5);  // 0,3,...,33  (12 groups, no clamp)
        const int gx  = x0 - 1 + rx;
        const int gy0 = y0 - 1 + ry3;

        const float* cb = &sm.comb[ry3][rx][0];   // window top-left for px0

        u64 acc[3][8];
        #pragma unroll
        for (int p = 0; p < 3; p++)
            #pragma unroll
            for (int j = 0; j < 8; j++) acc[p][j] = sm.bf2[j];

        #pragma unroll 2
        for (int c = 0; c < 17; c++) {
            const float* cc = cb + c;
            float v[15];   // 5 rows x 3 cols
            #pragma unroll
            for (int i = 0; i < 5; i++)
                #pragma unroll
                for (int j = 0; j < 3; j++)
                    v[i * 3 + j] = cc[(i * CWD + j) * 17];
            #pragma unroll
            for (int k = 0; k < 9; k++) {
                const int dy = k / 3, dx = k % 3;
                u64 t0 = pack2(v[(dy + 0) * 3 + dx], v[(dy + 0) * 3 + dx]);
                u64 t1 = pack2(v[(dy + 1) * 3 + dx], v[(dy + 1) * 3 + dx]);
                u64 t2 = pack2(v[(dy + 2) * 3 + dx], v[(dy + 2) * 3 + dx]);
                #pragma unroll
                for (int q = 0; q < 4; q++) {
                    ulonglong2 w = sm.wf[c][k][q];
                    fma2(acc[0][2 * q],     w.x, t0);
                    fma2(acc[0][2 * q + 1], w.y, t0);
                    fma2(acc[1][2 * q],     w.x, t1);
                    fma2(acc[1][2 * q + 1], w.y, t1);
                    fma2(acc[2][2 * q],     w.x, t2);
                    fma2(acc[2][2 * q + 1], w.y, t2);
                }
            }
        }

        // relu
        float h[3][16];
        #pragma unroll
        for (int p = 0; p < 3; p++)
            #pragma unroll
            for (int j = 0; j < 8; j++) {
                float a, bq;
                unpack2(acc[p][j], a, bq);
                h[p][2 * j]     = fmaxf(a, 0.f);
                h[p][2 * j + 1] = fmaxf(bq, 0.f);
            }

        // up2: 1x1 16 -> 16 = delta (3 pixels share weight loads)
        u64 d[3][8];
        #pragma unroll
        for (int p = 0; p < 3; p++)
            #pragma unroll
            for (int j = 0; j < 8; j++) d[p][j] = sm.bu22[j];
        #pragma unroll
        for (int ci = 0; ci < 16; ci++) {
            u64 p0 = pack2(h[0][ci], h[0][ci]);
            u64 p1 = pack2(h[1][ci], h[1][ci]);
            u64 p2 = pack2(h[2][ci], h[2][ci]);
            #pragma unroll
            for (int q = 0; q < 4; q++) {
                ulonglong2 w = sm.wu2[ci][q];
                fma2(d[0][2 * q],     w.x, p0);
                fma2(d[0][2 * q + 1], w.y, p0);
                fma2(d[1][2 * q],     w.x, p1);
                fma2(d[1][2 * q + 1], w.y, p1);
                fma2(d[2][2 * q],     w.x, p2);
                fma2(d[2][2 * q + 1], w.y, p2);
            }
        }
        #pragma unroll
        for (int p = 0; p < 3; p++) {
            const bool vp = (unsigned)gx < W_ && (unsigned)(gy0 + p) < H_;
            float* dd = &sm.del[ry3 + p][rx][0];
            #pragma unroll
            for (int j = 0; j < 8; j++) {
                float e0, e1;
                unpack2(d[p][j], e0, e1);
                dd[2 * j]     = vp ? e0 : 0.f;
                dd[2 * j + 1] = vp ? e1 : 0.f;
            }
        }
    }
    __syncthreads();

    // ---- stage 3: tau conv3x3 (33->16) + gated blend, 3 vertical px/thread
    //      (360 threads = 30 cols x 12 groups, clamped to 34 rows) ----
    if (tid < 360) {
        const int ox  = tid % 30;
        const int g   = tid / 30;                    // 0..11
        const int oy3 = (3 * g < TH - 3) ? 3 * g : TH - 3;   // 0,3,...,30,31
        const int gx  = x0 + ox;

        const float* cb = &sm.comb[oy3 + 1][ox + 1][0];   // comb window base
        const float* db = &sm.del [oy3][ox][0];           // del window base

        u64 acc[3][8];
        #pragma unroll
        for (int p = 0; p < 3; p++)
            #pragma unroll
            for (int j = 0; j < 8; j++) acc[p][j] = sm.bt2[j];

        #pragma unroll 2
        for (int c = 0; c < 17; c++) {   // x + state channels from comb
            const float* cc = cb + c;
            float v[15];
            #pragma unroll
            for (int i = 0; i < 5; i++)
                #pragma unroll
                for (int j = 0; j < 3; j++)
                    v[i * 3 + j] = cc[(i * CWD + j) * 17];
            #pragma unroll
            for (int k = 0; k < 9; k++) {
                const int dy = k / 3, dx = k % 3;
                u64 t0 = pack2(v[(dy + 0) * 3 + dx], v[(dy + 0) * 3 + dx]);
                u64 t1 = pack2(v[(dy + 1) * 3 + dx], v[(dy + 1) * 3 + dx]);
                u64 t2 = pack2(v[(dy + 2) * 3 + dx], v[(dy + 2) * 3 + dx]);
                #pragma unroll
                for (int q = 0; q < 4; q++) {
                    ulonglong2 w = sm.wt[c][k][q];
                    fma2(acc[0][2 * q],     w.x, t0);
                    fma2(acc[0][2 * q + 1], w.y, t0);
                    fma2(acc[1][2 * q],     w.x, t1);
                    fma2(acc[1][2 * q + 1], w.y, t1);
                    fma2(acc[2][2 * q],     w.x, t2);
                    fma2(acc[2][2 * q + 1], w.y, t2);
                }
            }
        }
        #pragma unroll 2
        for (int c = 0; c < 16; c++) {   // delta channels from del
            const float* cc = db + c;
            float v[15];
            #pragma unroll
            for (int i = 0; i < 5; i++)
                #pragma unroll
                for (int j = 0; j < 3; j++)
                    v[i * 3 + j] = cc[(i * RW + j) * 17];
            #pragma unroll
            for (int k = 0; k < 9; k++) {
                const int dy = k / 3, dx = k % 3;
                u64 t0 = pack2(v[(dy + 0) * 3 + dx], v[(dy + 0) * 3 + dx]);
                u64 t1 = pack2(v[(dy + 1) * 3 + dx], v[(dy + 1) * 3 + dx]);
                u64 t2 = pack2(v[(dy + 2) * 3 + dx], v[(dy + 2) * 3 + dx]);
                #pragma unroll
                for (int q = 0; q < 4; q++) {
                    ulonglong2 w = sm.wt[17 + c][k][q];
                    fma2(acc[0][2 * q],     w.x, t0);
                    fma2(acc[0][2 * q + 1], w.y, t0);
                    fma2(acc[1][2 * q],     w.x, t1);
                    fma2(acc[1][2 * q + 1], w.y, t1);
                    fma2(acc[2][2 * q],     w.x, t2);
                    fma2(acc[2][2 * q + 1], w.y, t2);
                }
            }
        }

        // sigmoid gate + blend + store per pixel
        #pragma unroll
        for (int p = 0; p < 3; p++) {
            const int ty = oy3 + p;                   // tile row (<=33)
            const int gy = y0 + ty;
            if (gy < H_ && gx < W_) {
                const float* st = &sm.comb[ty + 2][ox + 2][1];
                const float* dl = &sm.del [ty + 1][ox + 1][0];
                float nv[16];
                #pragma unroll
                for (int j = 0; j < 8; j++) {
                    float z0, z1;
                    unpack2(acc[p][j], z0, z1);
                    float b0 = fminf(fmaxf(sigmoidf_(z0), 0.01f), 0.99f);
                    float b1 = fminf(fmaxf(sigmoidf_(z1), 0.01f), 0.99f);
                    nv[2 * j]     = b0 * st[2 * j]     + (1.f - b0) * dl[2 * j];
                    nv[2 * j + 1] = b1 * st[2 * j + 1] + (1.f - b1) * dl[2 * j + 1];
                }
                long pix = ((long)(b * H_ + gy)) * W_ + gx;
                sOut[pix * 4 + 0] = make_float4(nv[0],  nv[1],  nv[2],  nv[3]);
                sOut[pix * 4 + 1] = make_float4(nv[4],  nv[5],  nv[6],  nv[7]);
                sOut[pix * 4 + 2] = make_float4(nv[8],  nv[9],  nv[10], nv[11]);
                sOut[pix * 4 + 3] = make_float4(nv[12], nv[13], nv[14], nv[15]);
            }
        }
    }
}

extern "C" __global__ void zero_state() {
    long i = (long)blockIdx.x * blockDim.x + threadIdx.x;
    long n = (long)B_ * H_ * W_ * 4;
    if (i < n) g_state0[i] = make_float4(0.f, 0.f, 0.f, 0.f);
}

extern "C" __global__ void readout(const float4* __restrict__ s,
                                   const float* __restrict__ w_read,
                                   const float* __restrict__ b_read,
                                   float* __restrict__ out)
{
    long i = (long)blockIdx.x * blockDim.x + threadIdx.x;
    if (i >= (long)B_ * H_ * W_) return;
    float4 a0 = s[i * 4 + 0];
    float4 a1 = s[i * 4 + 1];
    float4 a2 = s[i * 4 + 2];
    float4 a3 = s[i * 4 + 3];
    float acc = b_read[0];
    acc += a0.x * w_read[0]  + a0.y * w_read[1]  + a0.z * w_read[2]  + a0.w * w_read[3];
    acc += a1.x * w_read[4]  + a1.y * w_read[5]  + a1.z * w_read[6]  + a1.w * w_read[7];
    acc += a2.x * w_read[8]  + a2.y * w_read[9]  + a2.z * w_read[10] + a2.w * w_read[11];
    acc += a3.x * w_read[12] + a3.y * w_read[13] + a3.z * w_read[14] + a3.w * w_read[15];
    out[i] = 1.0f / (1.0f + __expf(-acc));
}

extern "C" void kernel_launch(void* const* d_in, const int* in_sizes, int n_in,
                              void* d_out, int out_size)
{
    const float* x   = (const float*)d_in[0];
    const float* wp  = (const float*)d_in[1];
    const float* bp  = (const float*)d_in[2];
    const float* wu1 = (const float*)d_in[3];
    const float* bu1 = (const float*)d_in[4];
    const float* wu2 = (const float*)d_in[5];
    const float* bu2 = (const float*)d_in[6];
    const float* wt  = (const float*)d_in[7];
    const float* btc = (const float*)d_in[8];
    const float* bt  = (const float*)d_in[9];
    const float* wr  = (const float*)d_in[10];
    const float* br  = (const float*)d_in[11];
    float* out = (float*)d_out;

    cudaFuncSetAttribute(nca_step, cudaFuncAttributeMaxDynamicSharedMemorySize,
                         (int)sizeof(SM));

    float4 *s0, *s1;
    cudaGetSymbolAddress((void**)&s0, g_state0);
    cudaGetSymbolAddress((void**)&s1, g_state1);

    fuse_weights<<<10, 256>>>(wp, bp, wu1, bu1);

    long n4 = (long)B_ * H_ * W_ * 4;
    zero_state<<<(int)((n4 + 255) / 256), 256>>>();

    dim3 grid((W_ + TW - 1) / TW, (H_ + TH - 1) / TH, B_);
    float4* cur = s0;
    float4* nxt = s1;
    for (int s = 0; s < N_STEPS; s++) {
        nca_step<<<grid, NTHR, sizeof(SM)>>>(x, cur, nxt,
                                             wu2, bu2, wt, btc, bt);
        float4* t = cur; cur = nxt; nxt = t;
    }

    long npix = (long)B_ * H_ * W_;
    readout<<<(int)((npix + 255) / 256), 256>>>(cur, wr, br, out);
}

// round 14
// speedup vs baseline: 1.8060x; 1.1976x over previous
#include <cuda_runtime.h>

#define B_      32
#define H_      256
#define W_      256
#define TW      30          // output tile width
#define TH      43          // output tile height (6 tiles: 258 rows, 0.8% waste)
#define RW      32          // stage-2 region cols = TW+2
#define RH      45          // stage-2 region rows = TH+2 (= 15 groups of 3, exact)
#define CWD     34          // comb tile width  = TW+4
#define CHT     47          // comb tile height = TH+4
#define NTHR    480
#define N_STEPS 10

typedef unsigned long long u64;

// Ping-pong state, channels-last [B][H][W][16] as float4 x4
__device__ float4 g_state0[(size_t)B_ * H_ * W_ * 4];
__device__ float4 g_state1[(size_t)B_ * H_ * W_ * 4];
// Fused perceive->up1 weights: (W_up1 @ W_perceive): [16][17][9], bias [16]
__device__ float g_wf[16 * 17 * 9];
__device__ float g_bf[16];
// Staging buffers for packed weights (copied into __constant__ via D2D)
__device__ ulonglong2 g_pk_wf [17 * 9 * 4];
__device__ ulonglong2 g_pk_wt [33 * 9 * 4];
__device__ ulonglong2 g_pk_wu2[16 * 4];
__device__ u64        g_pk_b  [24];

// Constant-memory weights: warp-uniform reads go through the constant port,
// off the L1/shared path entirely.
__constant__ ulonglong2 c_wf [17][9][4];
__constant__ ulonglong2 c_wt [33][9][4];
__constant__ ulonglong2 c_wu2[16][4];
__constant__ u64        c_b  [24];     // [0:8) bf2, [8:16) bu22, [16:24) bt2

__device__ __forceinline__ u64 pack2(float lo, float hi) {
    u64 r;
    asm("mov.b64 %0, {%1, %2};" : "=l"(r) : "f"(lo), "f"(hi));
    return r;
}
__device__ __forceinline__ void unpack2(u64 v, float& lo, float& hi) {
    asm("mov.b64 {%0, %1}, %2;" : "=f"(lo), "=f"(hi) : "l"(v));
}
__device__ __forceinline__ void fma2(u64& acc, u64 a, u64 b) {
    asm("fma.rn.f32x2 %0, %1, %2, %0;" : "+l"(acc) : "l"(a), "l"(b));
}
__device__ __forceinline__ float sigmoidf_(float z) {
    return 1.0f / (1.0f + __expf(-z));
}

struct SM {
    float comb[CHT][CWD][17];     // x + state, halo 2 (stride 17 conflict-free)
    float del [16][RH][RW];       // delta, planar per-channel (conflict-free)
};

// ---- prep 1: fold up1 into perceive (both linear; relu is after up1) ----
extern "C" __global__ void fuse_weights(const float* __restrict__ wp,
                                        const float* __restrict__ bp,
                                        const float* __restrict__ w1,
                                        const float* __restrict__ b1)
{
    int i = blockIdx.x * blockDim.x + threadIdx.x;
    if (i < 16 * 153) {
        int o = i / 153, ck = i % 153;
        float s = 0.f;
        #pragma unroll
        for (int m = 0; m < 32; m++) s += w1[o * 32 + m] * wp[m * 153 + ck];
        g_wf[i] = s;
    }
    if (i < 16) {
        float s = b1[i];
        #pragma unroll
        for (int m = 0; m < 32; m++) s += w1[i * 32 + m] * bp[m];
        g_bf[i] = s;
    }
}

// ---- prep 2: pack all weights into staging (final constant layout) ----
extern "C" __global__ void pack_weights(const float* __restrict__ w_tau,
                                        const float* __restrict__ w_up2,
                                        const float* __restrict__ b_up2,
                                        const float* __restrict__ b_tauc,
                                        const float* __restrict__ b_tau)
{
    int i = blockIdx.x * blockDim.x + threadIdx.x;
    if (i < 612) {                       // fused conv 17x9x4
        int q = i & 3, k = (i >> 2) % 9, c = i / 36;
        int o = 4 * q;
        g_pk_wf[i] = make_ulonglong2(
            pack2(g_wf[(o + 0) * 153 + c * 9 + k], g_wf[(o + 1) * 153 + c * 9 + k]),
            pack2(g_wf[(o + 2) * 153 + c * 9 + k], g_wf[(o + 3) * 153 + c * 9 + k]));
    } else if (i < 1800) {               // tau 33x9x4
        int j = i - 612;
        int q = j & 3, k = (j >> 2) % 9, c = j / 36;
        int o = 4 * q;
        g_pk_wt[j] = make_ulonglong2(
            pack2(w_tau[(o + 0) * 297 + c * 9 + k], w_tau[(o + 1) * 297 + c * 9 + k]),
            pack2(w_tau[(o + 2) * 297 + c * 9 + k], w_tau[(o + 3) * 297 + c * 9 + k]));
    } else if (i < 1864) {               // up2 16x4
        int j = i - 1800;
        int q = j & 3, ci = j >> 2;
        int o = 4 * q;
        g_pk_wu2[j] = make_ulonglong2(
            pack2(w_up2[(o + 0) * 16 + ci], w_up2[(o + 1) * 16 + ci]),
            pack2(w_up2[(o + 2) * 16 + ci], w_up2[(o + 3) * 16 + ci]));
    } else if (i < 1872) {               // fused bias
        int j = i - 1864;
        g_pk_b[j] = pack2(g_bf[2 * j], g_bf[2 * j + 1]);
    } else if (i < 1880) {               // up2 bias
        int j = i - 1872;
        g_pk_b[8 + j] = pack2(b_up2[2 * j], b_up2[2 * j + 1]);
    } else if (i < 1888) {               // tau bias (conv + b_tau)
        int j = i - 1880;
        g_pk_b[16 + j] = pack2(b_tauc[2 * j] + b_tau[2 * j],
                               b_tauc[2 * j + 1] + b_tau[2 * j + 1]);
    }
}

extern "C" __global__ void __launch_bounds__(NTHR, 1)
nca_step(const float*  __restrict__ x,
         const float4* __restrict__ sIn,
         float4*       __restrict__ sOut)
{
    extern __shared__ char smraw[];
    SM& sm = *reinterpret_cast<SM*>(smraw);

    const int tid = threadIdx.x;
    const int x0 = blockIdx.x * TW;
    const int y0 = blockIdx.y * TH;
    const int b  = blockIdx.z;

    // ---- load combined = [x, state] tile with halo 2 (zero padded) ----
    for (int p = tid; p < CHT * CWD; p += NTHR) {
        int cy = p / CWD, cx = p % CWD;
        int gy = y0 - 2 + cy, gx = x0 - 2 + cx;
        float* dst = &sm.comb[cy][cx][0];
        if ((unsigned)gy < H_ && (unsigned)gx < W_) {
            long pix = ((long)(b * H_ + gy)) * W_ + gx;
            dst[0] = x[pix];
            float4 s0 = sIn[pix * 4 + 0];
            float4 s1 = sIn[pix * 4 + 1];
            float4 s2 = sIn[pix * 4 + 2];
            float4 s3 = sIn[pix * 4 + 3];
            dst[1] = s0.x;  dst[2] = s0.y;  dst[3] = s0.z;  dst[4] = s0.w;
            dst[5] = s1.x;  dst[6] = s1.y;  dst[7] = s1.z;  dst[8] = s1.w;
            dst[9] = s2.x;  dst[10] = s2.y; dst[11] = s2.z; dst[12] = s2.w;
            dst[13] = s3.x; dst[14] = s3.y; dst[15] = s3.z; dst[16] = s3.w;
        } else {
            #pragma unroll
            for (int c = 0; c < 17; c++) dst[c] = 0.f;
        }
    }
    __syncthreads();

    // ---- stage 2: fused conv(17->16)+relu+up2(16->16) over 32x45 region,
    //      3 vertical px / thread (480 thr = 32 cols x 15 groups, EXACT) ----
    {
        const int rx  = tid & 31;        // 0..31
        const int ry3 = 3 * (tid >> 5);  // 0,3,...,42 (15 groups, no clamp)
        const int gx  = x0 - 1 + rx;
        const int gy0 = y0 - 1 + ry3;

        const float* cb = &sm.comb[ry3][rx][0];   // window top-left for px0

        u64 acc[3][8];
        #pragma unroll
        for (int p = 0; p < 3; p++)
            #pragma unroll
            for (int j = 0; j < 8; j++) acc[p][j] = c_b[j];

        #pragma unroll 1
        for (int c = 0; c < 17; c++) {
            const float* cc = cb + c;
            float v[15];   // 5 rows x 3 cols
            #pragma unroll
            for (int i = 0; i < 5; i++)
                #pragma unroll
                for (int j = 0; j < 3; j++)
                    v[i * 3 + j] = cc[(i * CWD + j) * 17];
            #pragma unroll
            for (int k = 0; k < 9; k++) {
                const int dy = k / 3, dx = k % 3;
                u64 t0 = pack2(v[(dy + 0) * 3 + dx], v[(dy + 0) * 3 + dx]);
                u64 t1 = pack2(v[(dy + 1) * 3 + dx], v[(dy + 1) * 3 + dx]);
                u64 t2 = pack2(v[(dy + 2) * 3 + dx], v[(dy + 2) * 3 + dx]);
                #pragma unroll
                for (int q = 0; q < 4; q++) {
                    ulonglong2 w = c_wf[c][k][q];
                    fma2(acc[0][2 * q],     w.x, t0);
                    fma2(acc[0][2 * q + 1], w.y, t0);
                    fma2(acc[1][2 * q],     w.x, t1);
                    fma2(acc[1][2 * q + 1], w.y, t1);
                    fma2(acc[2][2 * q],     w.x, t2);
                    fma2(acc[2][2 * q + 1], w.y, t2);
                }
            }
        }

        // relu
        float h[3][16];
        #pragma unroll
        for (int p = 0; p < 3; p++)
            #pragma unroll
            for (int j = 0; j < 8; j++) {
                float a, bq;
                unpack2(acc[p][j], a, bq);
                h[p][2 * j]     = fmaxf(a, 0.f);
                h[p][2 * j + 1] = fmaxf(bq, 0.f);
            }

        // up2: 1x1 16 -> 16 = delta (3 pixels share weight loads)
        u64 d[3][8];
        #pragma unroll
        for (int p = 0; p < 3; p++)
            #pragma unroll
            for (int j = 0; j < 8; j++) d[p][j] = c_b[8 + j];
        #pragma unroll
        for (int ci = 0; ci < 16; ci++) {
            u64 p0 = pack2(h[0][ci], h[0][ci]);
            u64 p1 = pack2(h[1][ci], h[1][ci]);
            u64 p2 = pack2(h[2][ci], h[2][ci]);
            #pragma unroll
            for (int q = 0; q < 4; q++) {
                ulonglong2 w = c_wu2[ci][q];
                fma2(d[0][2 * q],     w.x, p0);
                fma2(d[0][2 * q + 1], w.y, p0);
                fma2(d[1][2 * q],     w.x, p1);
                fma2(d[1][2 * q + 1], w.y, p1);
                fma2(d[2][2 * q],     w.x, p2);
                fma2(d[2][2 * q + 1], w.y, p2);
            }
        }
        #pragma unroll
        for (int p = 0; p < 3; p++) {
            const bool vp = (unsigned)gx < W_ && (unsigned)(gy0 + p) < H_;
            #pragma unroll
            for (int j = 0; j < 8; j++) {
                float e0, e1;
                unpack2(d[p][j], e0, e1);
                sm.del[2 * j][ry3 + p][rx]     = vp ? e0 : 0.f;
                sm.del[2 * j + 1][ry3 + p][rx] = vp ? e1 : 0.f;
            }
        }
    }
    __syncthreads();

    // ---- stage 3: tau conv3x3 (33->16) + gated blend, 3 vertical px/thread
    //      (450 threads = 30 cols x 15 groups, clamped to 43 rows) ----
    if (tid < 450) {
        const int ox  = tid % 30;
        const int g   = tid / 30;                    // 0..14
        const int oy3 = (3 * g < TH - 3) ? 3 * g : TH - 3;   // 0..39, 40
        const int gx  = x0 + ox;

        u64 acc[3][8];
        #pragma unroll
        for (int p = 0; p < 3; p++)
            #pragma unroll
            for (int j = 0; j < 8; j++) acc[p][j] = c_b[16 + j];

        const float* cb = &sm.comb[oy3 + 1][ox + 1][0];   // comb window base

        #pragma unroll 1
        for (int c = 0; c < 17; c++) {   // x + state channels from comb
            const float* cc = cb + c;
            float v[15];
            #pragma unroll
            for (int i = 0; i < 5; i++)
                #pragma unroll
                for (int j = 0; j < 3; j++)
                    v[i * 3 + j] = cc[(i * CWD + j) * 17];
            #pragma unroll
            for (int k = 0; k < 9; k++) {
                const int dy = k / 3, dx = k % 3;
                u64 t0 = pack2(v[(dy + 0) * 3 + dx], v[(dy + 0) * 3 + dx]);
                u64 t1 = pack2(v[(dy + 1) * 3 + dx], v[(dy + 1) * 3 + dx]);
                u64 t2 = pack2(v[(dy + 2) * 3 + dx], v[(dy + 2) * 3 + dx]);
                #pragma unroll
                for (int q = 0; q < 4; q++) {
                    ulonglong2 w = c_wt[c][k][q];
                    fma2(acc[0][2 * q],     w.x, t0);
                    fma2(acc[0][2 * q + 1], w.y, t0);
                    fma2(acc[1][2 * q],     w.x, t1);
                    fma2(acc[1][2 * q + 1], w.y, t1);
                    fma2(acc[2][2 * q],     w.x, t2);
                    fma2(acc[2][2 * q + 1], w.y, t2);
                }
            }
        }
        #pragma unroll 1
        for (int c = 0; c < 16; c++) {   // delta channels (planar)
            const float* cc = &sm.del[c][oy3][ox];
            float v[15];
            #pragma unroll
            for (int i = 0; i < 5; i++)
                #pragma unroll
                for (int j = 0; j < 3; j++)
                    v[i * 3 + j] = cc[i * RW + j];
            #pragma unroll
            for (int k = 0; k < 9; k++) {
                const int dy = k / 3, dx = k % 3;
                u64 t0 = pack2(v[(dy + 0) * 3 + dx], v[(dy + 0) * 3 + dx]);
                u64 t1 = pack2(v[(dy + 1) * 3 + dx], v[(dy + 1) * 3 + dx]);
                u64 t2 = pack2(v[(dy + 2) * 3 + dx], v[(dy + 2) * 3 + dx]);
                #pragma unroll
                for (int q = 0; q < 4; q++) {
                    ulonglong2 w = c_wt[17 + c][k][q];
                    fma2(acc[0][2 * q],     w.x, t0);
                    fma2(acc[0][2 * q + 1], w.y, t0);
                    fma2(acc[1][2 * q],     w.x, t1);
                    fma2(acc[1][2 * q + 1], w.y, t1);
                    fma2(acc[2][2 * q],     w.x, t2);
                    fma2(acc[2][2 * q + 1], w.y, t2);
                }
            }
        }

        // sigmoid gate + blend + store per pixel
        #pragma unroll
        for (int p = 0; p < 3; p++) {
            const int ty = oy3 + p;                   // tile row (<=42)
            const int gy = y0 + ty;
            if (gy < H_ && gx < W_) {
                const float* st = &sm.comb[ty + 2][ox + 2][1];
                float nv[16];
                #pragma unroll
                for (int j = 0; j < 8; j++) {
                    float z0, z1;
                    unpack2(acc[p][j], z0, z1);
                    float b0 = fminf(fmaxf(sigmoidf_(z0), 0.01f), 0.99f);
                    float b1 = fminf(fmaxf(sigmoidf_(z1), 0.01f), 0.99f);
                    float dl0 = sm.del[2 * j][ty + 1][ox + 1];
                    float dl1 = sm.del[2 * j + 1][ty + 1][ox + 1];
                    nv[2 * j]     = b0 * st[2 * j]     + (1.f - b0) * dl0;
                    nv[2 * j + 1] = b1 * st[2 * j + 1] + (1.f - b1) * dl1;
                }
                long pix = ((long)(b * H_ + gy)) * W_ + gx;
                sOut[pix * 4 + 0] = make_float4(nv[0],  nv[1],  nv[2],  nv[3]);
                sOut[pix * 4 + 1] = make_float4(nv[4],  nv[5],  nv[6],  nv[7]);
                sOut[pix * 4 + 2] = make_float4(nv[8],  nv[9],  nv[10], nv[11]);
                sOut[pix * 4 + 3] = make_float4(nv[12], nv[13], nv[14], nv[15]);
            }
        }
    }
}

extern "C" __global__ void zero_state() {
    long i = (long)blockIdx.x * blockDim.x + threadIdx.x;
    long n = (long)B_ * H_ * W_ * 4;
    if (i < n) g_state0[i] = make_float4(0.f, 0.f, 0.f, 0.f);
}

extern "C" __global__ void readout(const float4* __restrict__ s,
                                   const float* __restrict__ w_read,
                                   const float* __restrict__ b_read,
                                   float* __restrict__ out)
{
    long i = (long)blockIdx.x * blockDim.x + threadIdx.x;
    if (i >= (long)B_ * H_ * W_) return;
    float4 a0 = s[i * 4 + 0];
    float4 a1 = s[i * 4 + 1];
    float4 a2 = s[i * 4 + 2];
    float4 a3 = s[i * 4 + 3];
    float acc = b_read[0];
    acc += a0.x * w_read[0]  + a0.y * w_read[1]  + a0.z * w_read[2]  + a0.w * w_read[3];
    acc += a1.x * w_read[4]  + a1.y * w_read[5]  + a1.z * w_read[6]  + a1.w * w_read[7];
    acc += a2.x * w_read[8]  + a2.y * w_read[9]  + a2.z * w_read[10] + a2.w * w_read[11];
    acc += a3.x * w_read[12] + a3.y * w_read[13] + a3.z * w_read[14] + a3.w * w_read[15];
    out[i] = 1.0f / (1.0f + __expf(-acc));
}

extern "C" void kernel_launch(void* const* d_in, const int* in_sizes, int n_in,
                              void* d_out, int out_size)
{
    const float* x   = (const float*)d_in[0];
    const float* wp  = (const float*)d_in[1];
    const float* bp  = (const float*)d_in[2];
    const float* wu1 = (const float*)d_in[3];
    const float* bu1 = (const float*)d_in[4];
    const float* wu2 = (const float*)d_in[5];
    const float* bu2 = (const float*)d_in[6];
    const float* wt  = (const float*)d_in[7];
    const float* btc = (const float*)d_in[8];
    const float* bt  = (const float*)d_in[9];
    const float* wr  = (const float*)d_in[10];
    const float* br  = (const float*)d_in[11];
    float* out = (float*)d_out;

    cudaFuncSetAttribute(nca_step, cudaFuncAttributeMaxDynamicSharedMemorySize,
                         (int)sizeof(SM));

    float4 *s0, *s1;
    cudaGetSymbolAddress((void**)&s0, g_state0);
    cudaGetSymbolAddress((void**)&s1, g_state1);

    // prep: fuse, pack, then copy into constant memory (D2D, capturable)
    fuse_weights<<<10, 256>>>(wp, bp, wu1, bu1);
    pack_weights<<<8, 256>>>(wt, wu2, bu2, btc, bt);

    void *p_wf, *p_wt, *p_wu2, *p_b;
    cudaGetSymbolAddress(&p_wf,  g_pk_wf);
    cudaGetSymbolAddress(&p_wt,  g_pk_wt);
    cudaGetSymbolAddress(&p_wu2, g_pk_wu2);
    cudaGetSymbolAddress(&p_b,   g_pk_b);
    cudaMemcpyToSymbolAsync(c_wf,  p_wf,  sizeof(c_wf),  0, cudaMemcpyDeviceToDevice, 0);
    cudaMemcpyToSymbolAsync(c_wt,  p_wt,  sizeof(c_wt),  0, cudaMemcpyDeviceToDevice, 0);
    cudaMemcpyToSymbolAsync(c_wu2, p_wu2, sizeof(c_wu2), 0, cudaMemcpyDeviceToDevice, 0);
    cudaMemcpyToSymbolAsync(c_b,   p_b,   sizeof(c_b),   0, cudaMemcpyDeviceToDevice, 0);

    long n4 = (long)B_ * H_ * W_ * 4;
    zero_state<<<(int)((n4 + 255) / 256), 256>>>();

    dim3 grid((W_ + TW - 1) / TW, (H_ + TH - 1) / TH, B_);
    float4* cur = s0;
    float4* nxt = s1;
    for (int s = 0; s < N_STEPS; s++) {
        nca_step<<<grid, NTHR, sizeof(SM)>>>(x, cur, nxt);
        float4* t = cur; cur = nxt; nxt = t;
    }

    long npix = (long)B_ * H_ * W_;
    readout<<<(int)((npix + 255) / 256), 256>>>(cur, wr, br, out);
}

// round 15
// speedup vs baseline: 1.8414x; 1.0196x over previous
#include <cuda_runtime.h>

#define B_      32
#define H_      256
#define W_      256
#define TW      30          // output tile width
#define TH      43          // output tile height (6 tiles: 258 rows, 0.8% waste)
#define RW      32          // stage-2 region cols = TW+2
#define RH      45          // stage-2 region rows = TH+2 (= 15 groups of 3, exact)
#define CWD     34          // comb tile width  = TW+4
#define CHT     47          // comb tile height = TH+4
#define NTHR    480
#define N_STEPS 10

typedef unsigned long long u64;

// Ping-pong state, channels-last [B][H][W][16] as float4 x4
__device__ float4 g_state0[(size_t)B_ * H_ * W_ * 4];
__device__ float4 g_state1[(size_t)B_ * H_ * W_ * 4];
// Fused perceive->up1 weights: (W_up1 @ W_perceive): [16][17][9], bias [16]
__device__ float g_wf[16 * 17 * 9];
__device__ float g_bf[16];
// Staging buffers for packed weights (copied into __constant__ via D2D)
__device__ ulonglong2 g_pk_wf [17 * 9 * 4];
__device__ ulonglong2 g_pk_wt [33 * 9 * 4];
__device__ ulonglong2 g_pk_wu2[16 * 4];
__device__ u64        g_pk_b  [24];

// Constant-memory weights: warp-uniform reads go through the constant port,
// off the L1/shared path entirely.
__constant__ ulonglong2 c_wf [17][9][4];
__constant__ ulonglong2 c_wt [33][9][4];
__constant__ ulonglong2 c_wu2[16][4];
__constant__ u64        c_b  [24];     // [0:8) bf2, [8:16) bu22, [16:24) bt2

__device__ __forceinline__ u64 pack2(float lo, float hi) {
    u64 r;
    asm("mov.b64 %0, {%1, %2};" : "=l"(r) : "f"(lo), "f"(hi));
    return r;
}
__device__ __forceinline__ void unpack2(u64 v, float& lo, float& hi) {
    asm("mov.b64 {%0, %1}, %2;" : "=f"(lo), "=f"(hi) : "l"(v));
}
__device__ __forceinline__ void fma2(u64& acc, u64 a, u64 b) {
    asm("fma.rn.f32x2 %0, %1, %2, %0;" : "+l"(acc) : "l"(a), "l"(b));
}
__device__ __forceinline__ float sigmoidf_(float z) {
    return 1.0f / (1.0f + __expf(-z));
}

struct SM {
    float comb[CHT][CWD][17];     // x + state, halo 2 (stride 17 conflict-free)
    float del [16][RH][RW];       // delta, planar per-channel (conflict-free)
};

// ---- prep 1: fold up1 into perceive (both linear; relu is after up1) ----
extern "C" __global__ void fuse_weights(const float* __restrict__ wp,
                                        const float* __restrict__ bp,
                                        const float* __restrict__ w1,
                                        const float* __restrict__ b1)
{
    int i = blockIdx.x * blockDim.x + threadIdx.x;
    if (i < 16 * 153) {
        int o = i / 153, ck = i % 153;
        float s = 0.f;
        #pragma unroll
        for (int m = 0; m < 32; m++) s += w1[o * 32 + m] * wp[m * 153 + ck];
        g_wf[i] = s;
    }
    if (i < 16) {
        float s = b1[i];
        #pragma unroll
        for (int m = 0; m < 32; m++) s += w1[i * 32 + m] * bp[m];
        g_bf[i] = s;
    }
}

// ---- prep 2: pack all weights into staging (final constant layout) ----
extern "C" __global__ void pack_weights(const float* __restrict__ w_tau,
                                        const float* __restrict__ w_up2,
                                        const float* __restrict__ b_up2,
                                        const float* __restrict__ b_tauc,
                                        const float* __restrict__ b_tau)
{
    int i = blockIdx.x * blockDim.x + threadIdx.x;
    if (i < 612) {                       // fused conv 17x9x4
        int q = i & 3, k = (i >> 2) % 9, c = i / 36;
        int o = 4 * q;
        g_pk_wf[i] = make_ulonglong2(
            pack2(g_wf[(o + 0) * 153 + c * 9 + k], g_wf[(o + 1) * 153 + c * 9 + k]),
            pack2(g_wf[(o + 2) * 153 + c * 9 + k], g_wf[(o + 3) * 153 + c * 9 + k]));
    } else if (i < 1800) {               // tau 33x9x4
        int j = i - 612;
        int q = j & 3, k = (j >> 2) % 9, c = j / 36;
        int o = 4 * q;
        g_pk_wt[j] = make_ulonglong2(
            pack2(w_tau[(o + 0) * 297 + c * 9 + k], w_tau[(o + 1) * 297 + c * 9 + k]),
            pack2(w_tau[(o + 2) * 297 + c * 9 + k], w_tau[(o + 3) * 297 + c * 9 + k]));
    } else if (i < 1864) {               // up2 16x4
        int j = i - 1800;
        int q = j & 3, ci = j >> 2;
        int o = 4 * q;
        g_pk_wu2[j] = make_ulonglong2(
            pack2(w_up2[(o + 0) * 16 + ci], w_up2[(o + 1) * 16 + ci]),
            pack2(w_up2[(o + 2) * 16 + ci], w_up2[(o + 3) * 16 + ci]));
    } else if (i < 1872) {               // fused bias
        int j = i - 1864;
        g_pk_b[j] = pack2(g_bf[2 * j], g_bf[2 * j + 1]);
    } else if (i < 1880) {               // up2 bias
        int j = i - 1872;
        g_pk_b[8 + j] = pack2(b_up2[2 * j], b_up2[2 * j + 1]);
    } else if (i < 1888) {               // tau bias (conv + b_tau)
        int j = i - 1880;
        g_pk_b[16 + j] = pack2(b_tauc[2 * j] + b_tau[2 * j],
                               b_tauc[2 * j + 1] + b_tau[2 * j + 1]);
    }
}

extern "C" __global__ void __launch_bounds__(NTHR, 1)
nca_step(const float*  __restrict__ x,
         const float4* __restrict__ sIn,
         float4*       __restrict__ sOut)
{
    extern __shared__ char smraw[];
    SM& sm = *reinterpret_cast<SM*>(smraw);

    const int tid = threadIdx.x;
    const int x0 = blockIdx.x * TW;
    const int y0 = blockIdx.y * TH;
    const int b  = blockIdx.z;

    // ---- load combined = [x, state] tile with halo 2 (zero padded) ----
    for (int p = tid; p < CHT * CWD; p += NTHR) {
        int cy = p / CWD, cx = p % CWD;
        int gy = y0 - 2 + cy, gx = x0 - 2 + cx;
        float* dst = &sm.comb[cy][cx][0];
        if ((unsigned)gy < H_ && (unsigned)gx < W_) {
            long pix = ((long)(b * H_ + gy)) * W_ + gx;
            dst[0] = x[pix];
            float4 s0 = sIn[pix * 4 + 0];
            float4 s1 = sIn[pix * 4 + 1];
            float4 s2 = sIn[pix * 4 + 2];
            float4 s3 = sIn[pix * 4 + 3];
            dst[1] = s0.x;  dst[2] = s0.y;  dst[3] = s0.z;  dst[4] = s0.w;
            dst[5] = s1.x;  dst[6] = s1.y;  dst[7] = s1.z;  dst[8] = s1.w;
            dst[9] = s2.x;  dst[10] = s2.y; dst[11] = s2.z; dst[12] = s2.w;
            dst[13] = s3.x; dst[14] = s3.y; dst[15] = s3.z; dst[16] = s3.w;
        } else {
            #pragma unroll
            for (int c = 0; c < 17; c++) dst[c] = 0.f;
        }
    }
    __syncthreads();

    // ---- stage 2: fused conv(17->16)+relu+up2(16->16) over 32x45 region,
    //      3 vertical px / thread (480 thr = 32 cols x 15 groups, EXACT) ----
    {
        const int rx  = tid & 31;        // 0..31
        const int ry3 = 3 * (tid >> 5);  // 0,3,...,42 (15 groups, no clamp)
        const int gx  = x0 - 1 + rx;
        const int gy0 = y0 - 1 + ry3;

        const float* cb = &sm.comb[ry3][rx][0];   // window top-left for px0

        u64 acc[3][8];
        #pragma unroll
        for (int p = 0; p < 3; p++)
            #pragma unroll
            for (int j = 0; j < 8; j++) acc[p][j] = c_b[j];

        #pragma unroll 2
        for (int c = 0; c < 17; c++) {
            const float* cc = cb + c;
            float v[15];   // 5 rows x 3 cols
            #pragma unroll
            for (int i = 0; i < 5; i++)
                #pragma unroll
                for (int j = 0; j < 3; j++)
                    v[i * 3 + j] = cc[(i * CWD + j) * 17];
            #pragma unroll
            for (int k = 0; k < 9; k++) {
                const int dy = k / 3, dx = k % 3;
                u64 t0 = pack2(v[(dy + 0) * 3 + dx], v[(dy + 0) * 3 + dx]);
                u64 t1 = pack2(v[(dy + 1) * 3 + dx], v[(dy + 1) * 3 + dx]);
                u64 t2 = pack2(v[(dy + 2) * 3 + dx], v[(dy + 2) * 3 + dx]);
                #pragma unroll
                for (int q = 0; q < 4; q++) {
                    ulonglong2 w = c_wf[c][k][q];
                    fma2(acc[0][2 * q],     w.x, t0);
                    fma2(acc[0][2 * q + 1], w.y, t0);
                    fma2(acc[1][2 * q],     w.x, t1);
                    fma2(acc[1][2 * q + 1], w.y, t1);
                    fma2(acc[2][2 * q],     w.x, t2);
                    fma2(acc[2][2 * q + 1], w.y, t2);
                }
            }
        }

        // relu
        float h[3][16];
        #pragma unroll
        for (int p = 0; p < 3; p++)
            #pragma unroll
            for (int j = 0; j < 8; j++) {
                float a, bq;
                unpack2(acc[p][j], a, bq);
                h[p][2 * j]     = fmaxf(a, 0.f);
                h[p][2 * j + 1] = fmaxf(bq, 0.f);
            }

        // up2: 1x1 16 -> 16 = delta (3 pixels share weight loads)
        u64 d[3][8];
        #pragma unroll
        for (int p = 0; p < 3; p++)
            #pragma unroll
            for (int j = 0; j < 8; j++) d[p][j] = c_b[8 + j];
        #pragma unroll
        for (int ci = 0; ci < 16; ci++) {
            u64 p0 = pack2(h[0][ci], h[0][ci]);
            u64 p1 = pack2(h[1][ci], h[1][ci]);
            u64 p2 = pack2(h[2][ci], h[2][ci]);
            #pragma unroll
            for (int q = 0; q < 4; q++) {
                ulonglong2 w = c_wu2[ci][q];
                fma2(d[0][2 * q],     w.x, p0);
                fma2(d[0][2 * q + 1], w.y, p0);
                fma2(d[1][2 * q],     w.x, p1);
                fma2(d[1][2 * q + 1], w.y, p1);
                fma2(d[2][2 * q],     w.x, p2);
                fma2(d[2][2 * q + 1], w.y, p2);
            }
        }
        #pragma unroll
        for (int p = 0; p < 3; p++) {
            const bool vp = (unsigned)gx < W_ && (unsigned)(gy0 + p) < H_;
            #pragma unroll
            for (int j = 0; j < 8; j++) {
                float e0, e1;
                unpack2(d[p][j], e0, e1);
                sm.del[2 * j][ry3 + p][rx]     = vp ? e0 : 0.f;
                sm.del[2 * j + 1][ry3 + p][rx] = vp ? e1 : 0.f;
            }
        }
    }
    __syncthreads();

    // ---- stage 3: tau conv3x3 (33->16) + gated blend, 3 vertical px/thread
    //      (450 threads = 30 cols x 15 groups, clamped to 43 rows) ----
    if (tid < 450) {
        const int ox  = tid % 30;
        const int g   = tid / 30;                    // 0..14
        const int oy3 = (3 * g < TH - 3) ? 3 * g : TH - 3;   // 0..39, 40
        const int gx  = x0 + ox;

        u64 acc[3][8];
        #pragma unroll
        for (int p = 0; p < 3; p++)
            #pragma unroll
            for (int j = 0; j < 8; j++) acc[p][j] = c_b[16 + j];

        const float* cb = &sm.comb[oy3 + 1][ox + 1][0];   // comb window base

        #pragma unroll 2
        for (int c = 0; c < 17; c++) {   // x + state channels from comb
            const float* cc = cb + c;
            float v[15];
            #pragma unroll
            for (int i = 0; i < 5; i++)
                #pragma unroll
                for (int j = 0; j < 3; j++)
                    v[i * 3 + j] = cc[(i * CWD + j) * 17];
            #pragma unroll
            for (int k = 0; k < 9; k++) {
                const int dy = k / 3, dx = k % 3;
                u64 t0 = pack2(v[(dy + 0) * 3 + dx], v[(dy + 0) * 3 + dx]);
                u64 t1 = pack2(v[(dy + 1) * 3 + dx], v[(dy + 1) * 3 + dx]);
                u64 t2 = pack2(v[(dy + 2) * 3 + dx], v[(dy + 2) * 3 + dx]);
                #pragma unroll
                for (int q = 0; q < 4; q++) {
                    ulonglong2 w = c_wt[c][k][q];
                    fma2(acc[0][2 * q],     w.x, t0);
                    fma2(acc[0][2 * q + 1], w.y, t0);
                    fma2(acc[1][2 * q],     w.x, t1);
                    fma2(acc[1][2 * q + 1], w.y, t1);
                    fma2(acc[2][2 * q],     w.x, t2);
                    fma2(acc[2][2 * q + 1], w.y, t2);
                }
            }
        }
        #pragma unroll 2
        for (int c = 0; c < 16; c++) {   // delta channels (planar)
            const float* cc = &sm.del[c][oy3][ox];
            float v[15];
            #pragma unroll
            for (int i = 0; i < 5; i++)
                #pragma unroll
                for (int j = 0; j < 3; j++)
                    v[i * 3 + j] = cc[i * RW + j];
            #pragma unroll
            for (int k = 0; k < 9; k++) {
                const int dy = k / 3, dx = k % 3;
                u64 t0 = pack2(v[(dy + 0) * 3 + dx], v[(dy + 0) * 3 + dx]);
                u64 t1 = pack2(v[(dy + 1) * 3 + dx], v[(dy + 1) * 3 + dx]);
                u64 t2 = pack2(v[(dy + 2) * 3 + dx], v[(dy + 2) * 3 + dx]);
                #pragma unroll
                for (int q = 0; q < 4; q++) {
                    ulonglong2 w = c_wt[17 + c][k][q];
                    fma2(acc[0][2 * q],     w.x, t0);
                    fma2(acc[0][2 * q + 1], w.y, t0);
                    fma2(acc[1][2 * q],     w.x, t1);
                    fma2(acc[1][2 * q + 1], w.y, t1);
                    fma2(acc[2][2 * q],     w.x, t2);
                    fma2(acc[2][2 * q + 1], w.y, t2);
                }
            }
        }

        // sigmoid gate + blend + store per pixel
        #pragma unroll
        for (int p = 0; p < 3; p++) {
            const int ty = oy3 + p;                   // tile row (<=42)
            const int gy = y0 + ty;
            if (gy < H_ && gx < W_) {
                const float* st = &sm.comb[ty + 2][ox + 2][1];
                float nv[16];
                #pragma unroll
                for (int j = 0; j < 8; j++) {
                    float z0, z1;
                    unpack2(acc[p][j], z0, z1);
                    float b0 = fminf(fmaxf(sigmoidf_(z0), 0.01f), 0.99f);
                    float b1 = fminf(fmaxf(sigmoidf_(z1), 0.01f), 0.99f);
                    float dl0 = sm.del[2 * j][ty + 1][ox + 1];
                    float dl1 = sm.del[2 * j + 1][ty + 1][ox + 1];
                    nv[2 * j]     = b0 * st[2 * j]     + (1.f - b0) * dl0;
                    nv[2 * j + 1] = b1 * st[2 * j + 1] + (1.f - b1) * dl1;
                }
                long pix = ((long)(b * H_ + gy)) * W_ + gx;
                sOut[pix * 4 + 0] = make_float4(nv[0],  nv[1],  nv[2],  nv[3]);
                sOut[pix * 4 + 1] = make_float4(nv[4],  nv[5],  nv[6],  nv[7]);
                sOut[pix * 4 + 2] = make_float4(nv[8],  nv[9],  nv[10], nv[11]);
                sOut[pix * 4 + 3] = make_float4(nv[12], nv[13], nv[14], nv[15]);
            }
        }
    }
}

extern "C" __global__ void zero_state() {
    long i = (long)blockIdx.x * blockDim.x + threadIdx.x;
    long n = (long)B_ * H_ * W_ * 4;
    if (i < n) g_state0[i] = make_float4(0.f, 0.f, 0.f, 0.f);
}

extern "C" __global__ void readout(const float4* __restrict__ s,
                                   const float* __restrict__ w_read,
                                   const float* __restrict__ b_read,
                                   float* __restrict__ out)
{
    long i = (long)blockIdx.x * blockDim.x + threadIdx.x;
    if (i >= (long)B_ * H_ * W_) return;
    float4 a0 = s[i * 4 + 0];
    float4 a1 = s[i * 4 + 1];
    float4 a2 = s[i * 4 + 2];
    float4 a3 = s[i * 4 + 3];
    float acc = b_read[0];
    acc += a0.x * w_read[0]  + a0.y * w_read[1]  + a0.z * w_read[2]  + a0.w * w_read[3];
    acc += a1.x * w_read[4]  + a1.y * w_read[5]  + a1.z * w_read[6]  + a1.w * w_read[7];
    acc += a2.x * w_read[8]  + a2.y * w_read[9]  + a2.z * w_read[10] + a2.w * w_read[11];
    acc += a3.x * w_read[12] + a3.y * w_read[13] + a3.z * w_read[14] + a3.w * w_read[15];
    out[i] = 1.0f / (1.0f + __expf(-acc));
}

extern "C" void kernel_launch(void* const* d_in, const int* in_sizes, int n_in,
                              void* d_out, int out_size)
{
    const float* x   = (const float*)d_in[0];
    const float* wp  = (const float*)d_in[1];
    const float* bp  = (const float*)d_in[2];
    const float* wu1 = (const float*)d_in[3];
    const float* bu1 = (const float*)d_in[4];
    const float* wu2 = (const float*)d_in[5];
    const float* bu2 = (const float*)d_in[6];
    const float* wt  = (const float*)d_in[7];
    const float* btc = (const float*)d_in[8];
    const float* bt  = (const float*)d_in[9];
    const float* wr  = (const float*)d_in[10];
    const float* br  = (const float*)d_in[11];
    float* out = (float*)d_out;

    cudaFuncSetAttribute(nca_step, cudaFuncAttributeMaxDynamicSharedMemorySize,
                         (int)sizeof(SM));

    float4 *s0, *s1;
    cudaGetSymbolAddress((void**)&s0, g_state0);
    cudaGetSymbolAddress((void**)&s1, g_state1);

    // prep: fuse, pack, then copy into constant memory (D2D, capturable)
    fuse_weights<<<10, 256>>>(wp, bp, wu1, bu1);
    pack_weights<<<8, 256>>>(wt, wu2, bu2, btc, bt);

    void *p_wf, *p_wt, *p_wu2, *p_b;
    cudaGetSymbolAddress(&p_wf,  g_pk_wf);
    cudaGetSymbolAddress(&p_wt,  g_pk_wt);
    cudaGetSymbolAddress(&p_wu2, g_pk_wu2);
    cudaGetSymbolAddress(&p_b,   g_pk_b);
    cudaMemcpyToSymbolAsync(c_wf,  p_wf,  sizeof(c_wf),  0, cudaMemcpyDeviceToDevice, 0);
    cudaMemcpyToSymbolAsync(c_wt,  p_wt,  sizeof(c_wt),  0, cudaMemcpyDeviceToDevice, 0);
    cudaMemcpyToSymbolAsync(c_wu2, p_wu2, sizeof(c_wu2), 0, cudaMemcpyDeviceToDevice, 0);
    cudaMemcpyToSymbolAsync(c_b,   p_b,   sizeof(c_b),   0, cudaMemcpyDeviceToDevice, 0);

    long n4 = (long)B_ * H_ * W_ * 4;
    zero_state<<<(int)((n4 + 255) / 256), 256>>>();

    dim3 grid((W_ + TW - 1) / TW, (H_ + TH - 1) / TH, B_);
    float4* cur = s0;
    float4* nxt = s1;
    for (int s = 0; s < N_STEPS; s++) {
        nca_step<<<grid, NTHR, sizeof(SM)>>>(x, cur, nxt);
        float4* t = cur; cur = nxt; nxt = t;
    }

    long npix = (long)B_ * H_ * W_;
    readout<<<(int)((npix + 255) / 256), 256>>>(cur, wr, br, out);
}